// round 14
// baseline (speedup 1.0000x reference)
#include <cuda_runtime.h>
#include <cuda.h>
#include <cuda_bf16.h>
#include <cstdint>

#define N_B    16
#define C_DIM  512
#define HW_DIM 3136
#define D_DIM  512

// tcgen05 available only in the arch-specific (sm_103a/sm_100a) compile pass.
#if defined(__CUDA_ARCH_FEAT_SM103_ALL) || defined(__CUDA_ARCH_FEAT_SM100_ALL) || \
    (defined(__CUDA_ARCH_SPECIFIC__) && (__CUDA_ARCH_SPECIFIC__ == 1030 || __CUDA_ARCH_SPECIFIC__ == 1000))
#define HAS_TCGEN05 1
#else
#define HAS_TCGEN05 0
#endif

// ===================== scratch (__device__ globals; no allocs) =====================
__device__ __nv_bfloat16 g_xt_hi[(size_t)N_B * HW_DIM * C_DIM];  // [n][s][c]
__device__ __nv_bfloat16 g_xt_lo[(size_t)N_B * HW_DIM * C_DIM];
__device__ __nv_bfloat16 g_w_hi[3][(size_t)D_DIM * C_DIM];       // [qkv][d][c]
__device__ __nv_bfloat16 g_w_lo[3][(size_t)D_DIM * C_DIM];
__device__ __nv_bfloat16 g_q_hi[(size_t)N_B * D_DIM * HW_DIM];   // [n][d][s]
__device__ __nv_bfloat16 g_q_lo[(size_t)N_B * D_DIM * HW_DIM];
__device__ __nv_bfloat16 g_k_hi[(size_t)N_B * D_DIM * HW_DIM];   // [n][e][s]
__device__ __nv_bfloat16 g_k_lo[(size_t)N_B * D_DIM * HW_DIM];
__device__ __nv_bfloat16 g_v_hi[(size_t)N_B * HW_DIM * D_DIM];   // [n][s][d]
__device__ __nv_bfloat16 g_v_lo[(size_t)N_B * HW_DIM * D_DIM];
__device__ float         g_S[(size_t)N_B * D_DIM * D_DIM];       // [n][d][e]
__device__ __nv_bfloat16 g_att_hi[(size_t)N_B * D_DIM * D_DIM];  // [n][d][e]
__device__ __nv_bfloat16 g_att_lo[(size_t)N_B * D_DIM * D_DIM];

// ===================== PTX helpers =====================
__device__ __forceinline__ uint32_t smem_to_u32(const void* smem_ptr) {
    uint32_t addr;
    asm("{ .reg .u64 tmp; cvta.to.shared.u64 tmp, %1; cvt.u32.u64 %0, tmp; }"
        : "=r"(addr) : "l"(smem_ptr));
    return addr;
}
#define MBARRIER_INIT(mbar_smem_addr, count) \
    asm volatile("mbarrier.init.shared.b64 [%0], %1;" \
        :: "r"((uint32_t)(mbar_smem_addr)), "r"((uint32_t)(count)) : "memory")
#define MBARRIER_EXPECT_TX(mbar_smem_addr, tx_bytes) \
    asm volatile("mbarrier.arrive.expect_tx.shared.b64 _, [%0], %1;" \
        :: "r"((uint32_t)(mbar_smem_addr)), "r"((uint32_t)(tx_bytes)) : "memory")
__device__ __forceinline__ void mbarrier_inval(uint32_t mbar_smem_addr) {
    asm volatile("mbarrier.inval.shared.b64 [%0];" :: "r"(mbar_smem_addr) : "memory");
}
#define MBARRIER_WAIT_PARITY(mbar_smem_addr, phase_parity) do { \
    uint32_t _mbar = (uint32_t)(mbar_smem_addr); \
    uint32_t _parity = (uint32_t)(phase_parity); \
    uint32_t _done; \
    asm volatile("{\n\t.reg .pred p;\n\t" \
        "mbarrier.try_wait.parity.acquire.cta.shared::cta.b64 p, [%1], %2;\n\t" \
        "selp.b32 %0, 1, 0, p;\n\t}" \
        : "=r"(_done) : "r"(_mbar), "r"(_parity) : "memory"); \
    if (!_done) { \
        asm volatile("{\n\t.reg .pred P1;\n\t" \
            "WAIT_LOOP_%=:\n\t" \
            "mbarrier.try_wait.parity.acquire.cta.shared::cta.b64 P1, [%0], %1, 0x989680;\n\t" \
            "@P1 bra.uni WAIT_DONE_%=;\n\t" \
            "bra.uni WAIT_LOOP_%=;\n\t" \
            "WAIT_DONE_%=:\n\t}" \
            :: "r"(_mbar), "r"(_parity) : "memory"); \
    } \
} while(0)

#if HAS_TCGEN05
#define TCGEN05_ALLOC(smem_result_addr, nCols) \
    asm volatile("tcgen05.alloc.cta_group::1.sync.aligned.shared::cta.b32 [%0], %1;" \
        :: "r"((uint32_t)(smem_result_addr)), "r"((uint32_t)(nCols)) : "memory")
#define TCGEN05_DEALLOC(tmem_addr, nCols) \
    asm volatile("tcgen05.dealloc.cta_group::1.sync.aligned.b32 %0, %1;" \
        :: "r"(tmem_addr), "r"((uint32_t)(nCols)))
#define TCGEN05_RELINQUISH_ALLOC_PERMIT() \
    asm volatile("tcgen05.relinquish_alloc_permit.cta_group::1.sync.aligned;")
#define TCGEN05_COMMIT(mbar_smem_addr) \
    asm volatile("tcgen05.commit.cta_group::1.mbarrier::arrive::one.shared::cluster.b64 [%0];" \
        :: "r"((uint32_t)(mbar_smem_addr)) : "memory")
#define TCGEN05_FENCE_BEFORE() asm volatile("tcgen05.fence::before_thread_sync;" ::: "memory")
#define TCGEN05_FENCE_AFTER()  asm volatile("tcgen05.fence::after_thread_sync;" ::: "memory")
#define TCGEN05_WAIT_LD()      asm volatile("tcgen05.wait::ld.sync.aligned;" ::: "memory")
#define TCGEN05_LD_32X32B_X32(r, tmem_addr) \
    asm volatile("tcgen05.ld.sync.aligned.32x32b.x32.b32 " \
        "{%0, %1, %2, %3, %4, %5, %6, %7, %8, %9, %10, %11, %12, %13, %14, %15, " \
        " %16, %17, %18, %19, %20, %21, %22, %23, %24, %25, %26, %27, %28, %29, %30, %31}, [%32];" \
        : "=r"((r)[0]),  "=r"((r)[1]),  "=r"((r)[2]),  "=r"((r)[3]), \
          "=r"((r)[4]),  "=r"((r)[5]),  "=r"((r)[6]),  "=r"((r)[7]), \
          "=r"((r)[8]),  "=r"((r)[9]),  "=r"((r)[10]), "=r"((r)[11]), \
          "=r"((r)[12]), "=r"((r)[13]), "=r"((r)[14]), "=r"((r)[15]), \
          "=r"((r)[16]), "=r"((r)[17]), "=r"((r)[18]), "=r"((r)[19]), \
          "=r"((r)[20]), "=r"((r)[21]), "=r"((r)[22]), "=r"((r)[23]), \
          "=r"((r)[24]), "=r"((r)[25]), "=r"((r)[26]), "=r"((r)[27]), \
          "=r"((r)[28]), "=r"((r)[29]), "=r"((r)[30]), "=r"((r)[31]) \
        : "r"(tmem_addr))
#define TMA_LOAD_3D(smem_addr, tensor_map, cx, cy, cz, mbar) \
    asm volatile("cp.async.bulk.tensor.3d.shared::cta.global.tile.mbarrier::complete_tx::bytes " \
        "[%0], [%1, {%2, %3, %4}], [%5];" \
        :: "r"((uint32_t)(smem_addr)), "l"(tensor_map), \
           "r"((int32_t)(cx)), "r"((int32_t)(cy)), "r"((int32_t)(cz)), \
           "r"((uint32_t)(mbar)) : "memory")

// SW64 smem descriptor (64-byte rows, BK=32 bf16):
// layout_type=4 (SW64), version=1, SBO=32 (8 rows x 64B = 512B), LBO=1.
static constexpr uint64_t SMEM_DESC_BASE_SW64 =
    (uint64_t(4)  << 61) | (uint64_t(1) << 46) | (uint64_t(32) << 32) | (uint64_t(1) << 16);
#define MAKE_SMEM_DESC(base_addr) \
    (SMEM_DESC_BASE_SW64 | ((uint64_t)((base_addr) >> 4) & 0x3FFF))

// SS-mode cg1 kind::f16 MMA (bf16 in, fp32 accum)
__device__ __forceinline__ void mma_f16_ss(uint32_t d_tmem, uint64_t a_desc,
                                           uint64_t b_desc, uint32_t idesc, bool acc)
{
    uint32_t en = acc ? 1u : 0u;
    asm volatile(
        "{\n\t.reg .pred p;\n\tsetp.ne.u32 p, %4, 0;\n\t"
        "tcgen05.mma.cta_group::1.kind::f16 [%0], %1, %2, %3, {%5, %5, %5, %5}, p;\n\t}"
        :: "r"(d_tmem), "l"(a_desc), "l"(b_desc), "r"(idesc), "r"(en), "r"(0u)
        : "memory");
}
#endif // HAS_TCGEN05

// idesc: F32 accum (1<<4), A=BF16 (1<<7), B=BF16 (1<<10), N=256, M=128
static constexpr uint32_t IDESC_BF16_128x256 =
    (1u << 4) | (1u << 7) | (1u << 10) | ((256u / 8u) << 17) | ((128u / 16u) << 24);

// ===================== smem layout (dynamic) =====================
// BK=32 (64B rows, SW64): stage = Ahi 8K | Alo 8K | Bhi 16K | Blo 16K = 48 KB; 2 stages; 2 CTAs/SM.
static constexpr int NSTAGE    = 2;
static constexpr int OFF_TMEM  = 0;
static constexpr int OFF_FULLB = 8;                  // full[s] = 8 + 8s
static constexpr int OFF_DONEB = 24;                 // done[s] = 24 + 8s
static constexpr int OFF_BIAS  = 128;                // 256 f32 -> [128,1152)
static constexpr int OFF_DATA  = 2048;
static constexpr int STAGE_STRIDE = 49152;           // 48 KB
static constexpr int OFF_AHI = 0;
static constexpr int OFF_ALO = 8192;
static constexpr int OFF_BHI = 16384;
static constexpr int OFF_BLO = 32768;
static constexpr int SMEM_BYTES = OFF_DATA + NSTAGE * STAGE_STRIDE;  // 100352
static constexpr uint32_t TX_BYTES = 49152;

__device__ __forceinline__ void split_store(float v, __nv_bfloat16* hi, __nv_bfloat16* lo)
{
    __nv_bfloat16 h = __float2bfloat16(v);
    *hi = h;
    *lo = __float2bfloat16(v - __bfloat162float(h));
}

// =====================================================================
// TMA-fed GEMM on pre-split bf16 planes: C[m][n] = sum_k A[m][k]*B[n][k]
// (3-term split-bf16). 128x256 tile/CTA, BK=32 (SW64), 2-stage pipeline,
// 2 CTAs/SM (TMEM 256 cols each), warp-specialized producer/consumer.
// BIAS_MODE: 0=none, 1=bias[m], 2=bias[n]. OUT_BF16: write hi/lo planes.
// =====================================================================
template <int BIAS_MODE, bool OUT_BF16>
__global__ __launch_bounds__(256, 2)
void tc_gemm_tma(const __grid_constant__ CUtensorMap mapAhi,
                 const __grid_constant__ CUtensorMap mapAlo,
                 const __grid_constant__ CUtensorMap mapBhi,
                 const __grid_constant__ CUtensorMap mapBlo,
                 const __nv_bfloat16* __restrict__ Ahi,   // raw planes (fallback only)
                 const __nv_bfloat16* __restrict__ Alo,
                 const __nv_bfloat16* __restrict__ Bhi,
                 const __nv_bfloat16* __restrict__ Blo,
                 const float* __restrict__ bias,
                 float* __restrict__ Cf,
                 __nv_bfloat16* __restrict__ Chi,
                 __nv_bfloat16* __restrict__ Clo,
                 int M, int Nn, int K, int ldc,
                 long long strideA, long long strideB, long long strideC,
                 int zA, int zB)
{
    extern __shared__ char smem[];
    const int tid = threadIdx.x;
    const int n0 = blockIdx.x * 256;
    const int m0 = blockIdx.y * 128;

    if (Cf)  Cf  += strideC * blockIdx.z;
    if (Chi) { Chi += strideC * blockIdx.z; Clo += strideC * blockIdx.z; }

#if HAS_TCGEN05
    const uint32_t sb = smem_to_u32(smem);
    const int wid = tid >> 5;
    const int zcA = zA ? blockIdx.z : 0;
    const int zcB = zB ? blockIdx.z : 0;

    if (tid == 0) {
        #pragma unroll
        for (int s = 0; s < NSTAGE; s++) {
            MBARRIER_INIT(sb + OFF_FULLB + 8 * s, 1);
            MBARRIER_INIT(sb + OFF_DONEB + 8 * s, 1);
        }
    }
    if (wid == 0) {
        TCGEN05_ALLOC(sb + OFF_TMEM, 256);
        TCGEN05_RELINQUISH_ALLOC_PERMIT();
    }
    if (BIAS_MODE == 2) {
        int n = n0 + tid;
        *(float*)(smem + OFF_BIAS + tid * 4) = (n < Nn) ? bias[n] : 0.0f;
    }
    __syncthreads();

    uint32_t tmem;
    asm volatile("ld.shared.b32 %0, [%1];" : "=r"(tmem) : "r"(sb + OFF_TMEM));

    const int nc = K / 32;    // chunks of BK=32; >= 16 for all shapes here

    // ---- producer: warp 1 lane 0. Issues TMA; paced by done barriers. ----
    if (tid == 32) {
        int phD[NSTAGE] = {};
        auto issue = [&](int c) {
            const int st = c & (NSTAGE - 1);
            const uint32_t fb  = sb + OFF_FULLB + 8 * st;
            const uint32_t b32 = sb + OFF_DATA + st * STAGE_STRIDE;
            MBARRIER_EXPECT_TX(fb, TX_BYTES);
            const int kt = c * 32;
            TMA_LOAD_3D(b32 + OFF_AHI, &mapAhi, kt, m0, zcA, fb);
            TMA_LOAD_3D(b32 + OFF_ALO, &mapAlo, kt, m0, zcA, fb);
            TMA_LOAD_3D(b32 + OFF_BHI, &mapBhi, kt, n0, zcB, fb);
            TMA_LOAD_3D(b32 + OFF_BLO, &mapBlo, kt, n0, zcB, fb);
        };
        #pragma unroll
        for (int c = 0; c < NSTAGE; c++) issue(c);
        for (int c = NSTAGE; c < nc; c++) {
            const int st = c & (NSTAGE - 1);
            MBARRIER_WAIT_PARITY(sb + OFF_DONEB + 8 * st, phD[st]);
            phD[st] ^= 1;
            issue(c);
        }
        // drain: final commit per stage
        #pragma unroll
        for (int s = 0; s < NSTAGE; s++)
            MBARRIER_WAIT_PARITY(sb + OFF_DONEB + 8 * s, phD[s]);
    }

    // ---- consumer: warp 0 lane 0. Waits full; issues MMAs; commits. ----
    if (tid == 0) {
        int phF[NSTAGE] = {};
        for (int c = 0; c < nc; c++) {
            const int st = c & (NSTAGE - 1);
            const uint32_t fb = sb + OFF_FULLB + 8 * st;
            const uint32_t db = sb + OFF_DONEB + 8 * st;
            MBARRIER_WAIT_PARITY(fb, phF[st]);
            phF[st] ^= 1;

            const uint32_t b32 = sb + OFF_DATA + st * STAGE_STRIDE;
            const uint64_t dAh = MAKE_SMEM_DESC(b32 + OFF_AHI);
            const uint64_t dAl = MAKE_SMEM_DESC(b32 + OFF_ALO);
            const uint64_t dBh = MAKE_SMEM_DESC(b32 + OFF_BHI);
            const uint64_t dBl = MAKE_SMEM_DESC(b32 + OFF_BLO);
            #pragma unroll
            for (int ks = 0; ks < 2; ks++) {
                const uint64_t o = (uint64_t)(ks * 2);
                mma_f16_ss(tmem, dAh + o, dBh + o, IDESC_BF16_128x256,
                           !(c == 0 && ks == 0));
                mma_f16_ss(tmem, dAh + o, dBl + o, IDESC_BF16_128x256, true);
                mma_f16_ss(tmem, dAl + o, dBh + o, IDESC_BF16_128x256, true);
            }
            TCGEN05_COMMIT(db);
        }
    }

    __syncthreads();       // producer's drain guarantees all MMAs complete
    TCGEN05_FENCE_AFTER();

    // ---- epilogue: lanes 0..127 = M rows; TMEM cols 0..255 = N ----
    if (tid < 128) {
        const int m = m0 + tid;
        const bool mok = (m < M);
        const float bm = (BIAS_MODE == 1 && mok) ? bias[m] : 0.0f;
        const float* bs = (const float*)(smem + OFF_BIAS);
        #pragma unroll
        for (int b = 0; b < 8; b++) {
            uint32_t r[32];
            TCGEN05_LD_32X32B_X32(r, tmem + b * 32);
            TCGEN05_WAIT_LD();
            if (mok) {
                #pragma unroll
                for (int j = 0; j < 8; j++) {
                    const int nc2 = b * 32 + j * 4;
                    const int n = n0 + nc2;
                    if (n + 4 <= Nn) {
                        float v[4];
                        #pragma unroll
                        for (int e = 0; e < 4; e++) {
                            v[e] = __uint_as_float(r[j * 4 + e]);
                            if (BIAS_MODE == 1) v[e] += bm;
                            if (BIAS_MODE == 2) v[e] += bs[nc2 + e];
                        }
                        if (OUT_BF16) {
                            __nv_bfloat16 h[4], l[4];
                            #pragma unroll
                            for (int e = 0; e < 4; e++) {
                                h[e] = __float2bfloat16(v[e]);
                                l[e] = __float2bfloat16(v[e] - __bfloat162float(h[e]));
                            }
                            uint2 hp, lp;
                            memcpy(&hp.x, &h[0], 4); memcpy(&hp.y, &h[2], 4);
                            memcpy(&lp.x, &l[0], 4); memcpy(&lp.y, &l[2], 4);
                            *(uint2*)(Chi + (long long)m * ldc + n) = hp;
                            *(uint2*)(Clo + (long long)m * ldc + n) = lp;
                        } else {
                            float4 o; o.x = v[0]; o.y = v[1]; o.z = v[2]; o.w = v[3];
                            *(float4*)(Cf + (long long)m * ldc + n) = o;
                        }
                    }
                }
            }
        }
    }
    TCGEN05_FENCE_BEFORE();
    __syncthreads();
    if (tid == 0) {
        #pragma unroll
        for (int s = 0; s < NSTAGE; s++) {
            mbarrier_inval(sb + OFF_FULLB + 8 * s);
            mbarrier_inval(sb + OFF_DONEB + 8 * s);
        }
    }
    if (wid == 0) TCGEN05_DEALLOC(tmem, 256);

#else  // ===== SIMT fallback (plain sm_103 pass; never runs on GB300) =====
    Ahi += strideA * blockIdx.z;  Alo += strideA * blockIdx.z;
    Bhi += strideB * blockIdx.z;  Blo += strideB * blockIdx.z;
    for (int idx = tid; idx < 128 * 256; idx += 256) {
        const int i = idx >> 8, j = idx & 255;
        const int m = m0 + i, n = n0 + j;
        if (m < M && n < Nn) {
            float acc = 0.f;
            for (int k = 0; k < K; k++) {
                float a = __bfloat162float(Ahi[(long long)m * K + k]) +
                          __bfloat162float(Alo[(long long)m * K + k]);
                float b = __bfloat162float(Bhi[(long long)n * K + k]) +
                          __bfloat162float(Blo[(long long)n * K + k]);
                acc += a * b;
            }
            if (BIAS_MODE == 1) acc += bias[m];
            if (BIAS_MODE == 2) acc += bias[n];
            if (OUT_BF16)
                split_store(acc, Chi + (long long)m * ldc + n, Clo + (long long)m * ldc + n);
            else
                Cf[(long long)m * ldc + n] = acc;
        }
    }
#endif
}

// ===================== transpose + split x: [n][c][hw] -> [n][hw][c] =====================
__global__ __launch_bounds__(256)
void transpose_split_x(const float* __restrict__ bf,
                       __nv_bfloat16* __restrict__ xhi,
                       __nv_bfloat16* __restrict__ xlo)
{
    __shared__ float t[64][65];
    const int n = blockIdx.z;
    const int hw0 = blockIdx.x * 64;
    const int c0 = blockIdx.y * 64;
    const int tid = threadIdx.x;

    const float* src = bf + (size_t)n * C_DIM * HW_DIM;
    {
        const int r  = tid >> 2;
        const int cb = (tid & 3) * 16;
        const float* p = src + (size_t)(c0 + r) * HW_DIM + hw0 + cb;
        #pragma unroll
        for (int i = 0; i < 4; i++) {
            float4 v = *(const float4*)(p + i * 4);
            t[r][cb + i * 4 + 0] = v.x;
            t[r][cb + i * 4 + 1] = v.y;
            t[r][cb + i * 4 + 2] = v.z;
            t[r][cb + i * 4 + 3] = v.w;
        }
    }
    __syncthreads();
    {
        const int sl   = tid >> 2;
        const int cseg = (tid & 3) * 16;
        __nv_bfloat16 h[16], l[16];
        #pragma unroll
        for (int j = 0; j < 16; j++) {
            const float v = t[cseg + j][sl];
            h[j] = __float2bfloat16(v);
            l[j] = __float2bfloat16(v - __bfloat162float(h[j]));
        }
        const size_t o = (size_t)n * HW_DIM * C_DIM +
                         (size_t)(hw0 + sl) * C_DIM + c0 + cseg;
        uint4 hv0, hv1, lv0, lv1;
        memcpy(&hv0, &h[0], 16); memcpy(&hv1, &h[8], 16);
        memcpy(&lv0, &l[0], 16); memcpy(&lv1, &l[8], 16);
        *(uint4*)(xhi + o)     = hv0;
        *(uint4*)(xhi + o + 8) = hv1;
        *(uint4*)(xlo + o)     = lv0;
        *(uint4*)(xlo + o + 8) = lv1;
    }
}

// ===================== split W (all three weights, one launch, vectorized) =====================
__global__ __launch_bounds__(256)
void split_w3(const float* __restrict__ Wq, const float* __restrict__ Wk,
              const float* __restrict__ Wv,
              __nv_bfloat16* __restrict__ whi, __nv_bfloat16* __restrict__ wlo)
{
    const int which = blockIdx.y;
    const float* W = (which == 0) ? Wq : (which == 1) ? Wk : Wv;
    const size_t base = (size_t)which * D_DIM * C_DIM;
    const int i4 = (blockIdx.x * 256 + threadIdx.x) * 4;
    if (i4 < D_DIM * C_DIM) {
        float4 v = *(const float4*)(W + i4);
        __nv_bfloat16 h[4], l[4];
        float f[4] = {v.x, v.y, v.z, v.w};
        #pragma unroll
        for (int e = 0; e < 4; e++) {
            h[e] = __float2bfloat16(f[e]);
            l[e] = __float2bfloat16(f[e] - __bfloat162float(h[e]));
        }
        uint2 hp, lp;
        memcpy(&hp, &h[0], 8);
        memcpy(&lp, &l[0], 8);
        *(uint2*)(whi + base + i4) = hp;
        *(uint2*)(wlo + base + i4) = lp;
    }
}

// ===================== softmax rows of 512 -> bf16 hi/lo planes =====================
__global__ __launch_bounds__(128)
void softmax_split(const float* __restrict__ S,
                   __nv_bfloat16* __restrict__ ahi, __nv_bfloat16* __restrict__ alo)
{
    const long long row = blockIdx.x;
    const float* p = S + row * D_DIM;
    const int t = threadIdx.x;

    float4 v = *(const float4*)(p + t * 4);
    float f[4] = {v.x, v.y, v.z, v.w};

    __shared__ float red_max[4];
    __shared__ float red_sum[4];

    float m = fmaxf(fmaxf(f[0], f[1]), fmaxf(f[2], f[3]));
    #pragma unroll
    for (int o = 16; o > 0; o >>= 1)
        m = fmaxf(m, __shfl_xor_sync(0xffffffffu, m, o));
    if ((t & 31) == 0) red_max[t >> 5] = m;
    __syncthreads();
    float rowmax = fmaxf(fmaxf(red_max[0], red_max[1]), fmaxf(red_max[2], red_max[3]));

    float e[4];
    #pragma unroll
    for (int i = 0; i < 4; i++) e[i] = __expf(f[i] - rowmax);
    float s = e[0] + e[1] + e[2] + e[3];
    #pragma unroll
    for (int o = 16; o > 0; o >>= 1)
        s += __shfl_xor_sync(0xffffffffu, s, o);
    if ((t & 31) == 0) red_sum[t >> 5] = s;
    __syncthreads();
    const float inv = 1.0f / (red_sum[0] + red_sum[1] + red_sum[2] + red_sum[3]);

    __nv_bfloat16 h[4], l[4];
    #pragma unroll
    for (int i = 0; i < 4; i++) {
        const float pv = e[i] * inv;
        h[i] = __float2bfloat16(pv);
        l[i] = __float2bfloat16(pv - __bfloat162float(h[i]));
    }
    uint2 hp, lp;
    memcpy(&hp, &h[0], 8);
    memcpy(&lp, &l[0], 8);
    *(uint2*)(ahi + row * D_DIM + t * 4) = hp;
    *(uint2*)(alo + row * D_DIM + t * 4) = lp;
}

// ===================== host: tensormap encode via driver entry point =====================
typedef CUresult (*EncodeTiledFn)(
    CUtensorMap*, CUtensorMapDataType, cuuint32_t, void*,
    const cuuint64_t*, const cuuint64_t*, const cuuint32_t*, const cuuint32_t*,
    CUtensorMapInterleave, CUtensorMapSwizzle, CUtensorMapL2promotion,
    CUtensorMapFloatOOBfill);

static EncodeTiledFn get_encode_fn()
{
    static EncodeTiledFn fn = nullptr;
    if (!fn) {
        cudaDriverEntryPointQueryResult st;
        void* p = nullptr;
        cudaGetDriverEntryPoint("cuTensorMapEncodeTiled", &p,
                                cudaEnableDefault, &st);
        fn = (EncodeTiledFn)p;
    }
    return fn;
}

// 3D bf16 map: dims [K elems, rows, batch]; box [32, boxRows, 1]; SWIZZLE_64B.
static void make_map(CUtensorMap* m, const void* base,
                     unsigned long long K, unsigned long long rows,
                     unsigned long long batch, unsigned boxRows)
{
    cuuint64_t dims[3]    = {K, rows, batch};
    cuuint64_t strides[2] = {K * 2ull, K * rows * 2ull};
    cuuint32_t box[3]     = {32u, boxRows, 1u};
    cuuint32_t es[3]      = {1u, 1u, 1u};
    get_encode_fn()(m, CU_TENSOR_MAP_DATA_TYPE_BFLOAT16, 3, (void*)base,
                    dims, strides, box, es,
                    CU_TENSOR_MAP_INTERLEAVE_NONE, CU_TENSOR_MAP_SWIZZLE_64B,
                    CU_TENSOR_MAP_L2_PROMOTION_L2_128B,
                    CU_TENSOR_MAP_FLOAT_OOB_FILL_NONE);
}

extern "C" void kernel_launch(void* const* d_in, const int* in_sizes, int n_in,
                              void* d_out, int out_size)
{
    (void)in_sizes; (void)n_in; (void)out_size;
    const float* bf = (const float*)d_in[0];  // [N, C, HW]
    const float* Wq = (const float*)d_in[1];  // [D, C]
    const float* bq = (const float*)d_in[2];  // [D]
    const float* Wk = (const float*)d_in[3];
    const float* bk = (const float*)d_in[4];
    const float* Wv = (const float*)d_in[5];
    const float* bv = (const float*)d_in[6];
    float* out = (float*)d_out;               // [N, D, HW]

    __nv_bfloat16 *xh, *xl, *wh, *wl, *qh, *ql, *kh, *kl, *vh, *vl, *ah, *al;
    float *Sp;
    cudaGetSymbolAddress((void**)&xh, g_xt_hi);
    cudaGetSymbolAddress((void**)&xl, g_xt_lo);
    cudaGetSymbolAddress((void**)&wh, g_w_hi);
    cudaGetSymbolAddress((void**)&wl, g_w_lo);
    cudaGetSymbolAddress((void**)&qh, g_q_hi);
    cudaGetSymbolAddress((void**)&ql, g_q_lo);
    cudaGetSymbolAddress((void**)&kh, g_k_hi);
    cudaGetSymbolAddress((void**)&kl, g_k_lo);
    cudaGetSymbolAddress((void**)&vh, g_v_hi);
    cudaGetSymbolAddress((void**)&vl, g_v_lo);
    cudaGetSymbolAddress((void**)&ah, g_att_hi);
    cudaGetSymbolAddress((void**)&al, g_att_lo);
    cudaGetSymbolAddress((void**)&Sp, g_S);

    cudaFuncSetAttribute(tc_gemm_tma<1, true>,
        cudaFuncAttributeMaxDynamicSharedMemorySize, SMEM_BYTES);
    cudaFuncSetAttribute(tc_gemm_tma<2, true>,
        cudaFuncAttributeMaxDynamicSharedMemorySize, SMEM_BYTES);
    cudaFuncSetAttribute(tc_gemm_tma<0, false>,
        cudaFuncAttributeMaxDynamicSharedMemorySize, SMEM_BYTES);

    const dim3 blk(256);
    const size_t WSZ = (size_t)D_DIM * C_DIM;
    const long long sX  = (long long)HW_DIM * C_DIM;
    const long long sQ  = (long long)D_DIM * HW_DIM;
    const long long sV  = (long long)HW_DIM * D_DIM;
    const long long sS  = (long long)D_DIM * D_DIM;

    // 0) splits/transposes
    transpose_split_x<<<dim3(HW_DIM / 64, C_DIM / 64, N_B), blk>>>(bf, xh, xl);
    split_w3<<<dim3((D_DIM * C_DIM / 4 + 255) / 256, 3), blk>>>(Wq, Wk, Wv, wh, wl);

    // tensormaps
    CUtensorMap mWq_h, mWq_l, mWk_h, mWk_l, mWv_h, mWv_l;
    CUtensorMap mXa_h, mXa_l, mXb_h, mXb_l;
    CUtensorMap mQ_h, mQ_l, mK_h, mK_l;
    CUtensorMap mV_h, mV_l, mAtt_h, mAtt_l;
    make_map(&mWq_h, wh + 0 * WSZ, C_DIM, D_DIM, 1, 128);
    make_map(&mWq_l, wl + 0 * WSZ, C_DIM, D_DIM, 1, 128);
    make_map(&mWk_h, wh + 1 * WSZ, C_DIM, D_DIM, 1, 128);
    make_map(&mWk_l, wl + 1 * WSZ, C_DIM, D_DIM, 1, 128);
    make_map(&mWv_h, wh + 2 * WSZ, C_DIM, D_DIM, 1, 256);
    make_map(&mWv_l, wl + 2 * WSZ, C_DIM, D_DIM, 1, 256);
    make_map(&mXb_h, xh, C_DIM, HW_DIM, N_B, 256);
    make_map(&mXb_l, xl, C_DIM, HW_DIM, N_B, 256);
    make_map(&mXa_h, xh, C_DIM, HW_DIM, N_B, 128);
    make_map(&mXa_l, xl, C_DIM, HW_DIM, N_B, 128);
    make_map(&mQ_h, qh, HW_DIM, D_DIM, N_B, 128);
    make_map(&mQ_l, ql, HW_DIM, D_DIM, N_B, 128);
    make_map(&mK_h, kh, HW_DIM, D_DIM, N_B, 256);
    make_map(&mK_l, kl, HW_DIM, D_DIM, N_B, 256);
    make_map(&mV_h, vh, D_DIM, HW_DIM, N_B, 256);
    make_map(&mV_l, vl, D_DIM, HW_DIM, N_B, 256);
    make_map(&mAtt_h, ah, D_DIM, D_DIM, N_B, 128);
    make_map(&mAtt_l, al, D_DIM, D_DIM, N_B, 128);

    // 1) Q/K proj: M=d(512), N=s(3136), K=c(512). A=W (batch-invariant), B=xT.
    const dim3 g_qk((HW_DIM + 255) / 256, D_DIM / 128, N_B);      // (13, 4, 16)
    tc_gemm_tma<1, true><<<g_qk, blk, SMEM_BYTES>>>(
        mWq_h, mWq_l, mXb_h, mXb_l,
        wh + 0 * WSZ, wl + 0 * WSZ, xh, xl, bq, nullptr, qh, ql,
        D_DIM, HW_DIM, C_DIM, HW_DIM, 0, sX, sQ, 0, 1);
    tc_gemm_tma<1, true><<<g_qk, blk, SMEM_BYTES>>>(
        mWk_h, mWk_l, mXb_h, mXb_l,
        wh + 1 * WSZ, wl + 1 * WSZ, xh, xl, bk, nullptr, kh, kl,
        D_DIM, HW_DIM, C_DIM, HW_DIM, 0, sX, sQ, 0, 1);

    // 1b) V proj: M=s(3136), N=d(512), K=c(512). A=xT, B=Wv.
    const dim3 g_v(D_DIM / 256, (HW_DIM + 127) / 128, N_B);       // (2, 25, 16)
    tc_gemm_tma<2, true><<<g_v, blk, SMEM_BYTES>>>(
        mXa_h, mXa_l, mWv_h, mWv_l,
        xh, xl, wh + 2 * WSZ, wl + 2 * WSZ, bv, nullptr, vh, vl,
        HW_DIM, D_DIM, C_DIM, D_DIM, sX, 0, sV, 1, 0);

    // 2) scores: M=d, N=e, K=s(3136). A=Q planes, B=K planes. Out fp32 S.
    const dim3 g_sc(D_DIM / 256, D_DIM / 128, N_B);               // (2, 4, 16)
    tc_gemm_tma<0, false><<<g_sc, blk, SMEM_BYTES>>>(
        mQ_h, mQ_l, mK_h, mK_l,
        qh, ql, kh, kl, nullptr, Sp, nullptr, nullptr,
        D_DIM, D_DIM, HW_DIM, D_DIM, sQ, sQ, sS, 1, 1);

    // 3) softmax -> att planes
    softmax_split<<<N_B * D_DIM, 128>>>(Sp, ah, al);

    // 4) out: M=d, N=s(3136), K=e(512). A=att planes, B=V planes. Out fp32.
    const dim3 g_out((HW_DIM + 255) / 256, D_DIM / 128, N_B);     // (13, 4, 16)
    tc_gemm_tma<0, false><<<g_out, blk, SMEM_BYTES>>>(
        mAtt_h, mAtt_l, mV_h, mV_l,
        ah, al, vh, vl, nullptr, out, nullptr, nullptr,
        D_DIM, HW_DIM, D_DIM, HW_DIM, sS, sV, (long long)D_DIM * HW_DIM, 1, 1);
}

// round 15
// speedup vs baseline: 1.0798x; 1.0798x over previous
#include <cuda_runtime.h>
#include <cuda.h>
#include <cuda_bf16.h>
#include <cstdint>

#define N_B    16
#define C_DIM  512
#define HW_DIM 3136
#define D_DIM  512

// tcgen05 available only in the arch-specific (sm_103a/sm_100a) compile pass.
#if defined(__CUDA_ARCH_FEAT_SM103_ALL) || defined(__CUDA_ARCH_FEAT_SM100_ALL) || \
    (defined(__CUDA_ARCH_SPECIFIC__) && (__CUDA_ARCH_SPECIFIC__ == 1030 || __CUDA_ARCH_SPECIFIC__ == 1000))
#define HAS_TCGEN05 1
#else
#define HAS_TCGEN05 0
#endif

// ===================== scratch (__device__ globals; no allocs) =====================
__device__ __nv_bfloat16 g_xt_hi[(size_t)N_B * HW_DIM * C_DIM];  // [n][s][c]
__device__ __nv_bfloat16 g_xt_lo[(size_t)N_B * HW_DIM * C_DIM];
__device__ __nv_bfloat16 g_w_hi[3][(size_t)D_DIM * C_DIM];       // [qkv][d][c]
__device__ __nv_bfloat16 g_w_lo[3][(size_t)D_DIM * C_DIM];
__device__ __nv_bfloat16 g_q_hi[(size_t)N_B * D_DIM * HW_DIM];   // [n][d][s]
__device__ __nv_bfloat16 g_q_lo[(size_t)N_B * D_DIM * HW_DIM];
__device__ __nv_bfloat16 g_k_hi[(size_t)N_B * D_DIM * HW_DIM];   // [n][e][s]
__device__ __nv_bfloat16 g_k_lo[(size_t)N_B * D_DIM * HW_DIM];
__device__ __nv_bfloat16 g_v_hi[(size_t)N_B * HW_DIM * D_DIM];   // [n][s][d]
__device__ __nv_bfloat16 g_v_lo[(size_t)N_B * HW_DIM * D_DIM];
__device__ float         g_S[(size_t)N_B * D_DIM * D_DIM];       // [n][d][e]
__device__ __nv_bfloat16 g_att_hi[(size_t)N_B * D_DIM * D_DIM];  // [n][d][e]
__device__ __nv_bfloat16 g_att_lo[(size_t)N_B * D_DIM * D_DIM];

// ===================== PTX helpers =====================
__device__ __forceinline__ uint32_t smem_to_u32(const void* smem_ptr) {
    uint32_t addr;
    asm("{ .reg .u64 tmp; cvta.to.shared.u64 tmp, %1; cvt.u32.u64 %0, tmp; }"
        : "=r"(addr) : "l"(smem_ptr));
    return addr;
}
#define MBARRIER_INIT(mbar_smem_addr, count) \
    asm volatile("mbarrier.init.shared.b64 [%0], %1;" \
        :: "r"((uint32_t)(mbar_smem_addr)), "r"((uint32_t)(count)) : "memory")
#define MBARRIER_EXPECT_TX(mbar_smem_addr, tx_bytes) \
    asm volatile("mbarrier.arrive.expect_tx.shared.b64 _, [%0], %1;" \
        :: "r"((uint32_t)(mbar_smem_addr)), "r"((uint32_t)(tx_bytes)) : "memory")
__device__ __forceinline__ void mbarrier_inval(uint32_t mbar_smem_addr) {
    asm volatile("mbarrier.inval.shared.b64 [%0];" :: "r"(mbar_smem_addr) : "memory");
}
#define MBARRIER_WAIT_PARITY(mbar_smem_addr, phase_parity) do { \
    uint32_t _mbar = (uint32_t)(mbar_smem_addr); \
    uint32_t _parity = (uint32_t)(phase_parity); \
    uint32_t _done; \
    asm volatile("{\n\t.reg .pred p;\n\t" \
        "mbarrier.try_wait.parity.acquire.cta.shared::cta.b64 p, [%1], %2;\n\t" \
        "selp.b32 %0, 1, 0, p;\n\t}" \
        : "=r"(_done) : "r"(_mbar), "r"(_parity) : "memory"); \
    if (!_done) { \
        asm volatile("{\n\t.reg .pred P1;\n\t" \
            "WAIT_LOOP_%=:\n\t" \
            "mbarrier.try_wait.parity.acquire.cta.shared::cta.b64 P1, [%0], %1, 0x989680;\n\t" \
            "@P1 bra.uni WAIT_DONE_%=;\n\t" \
            "bra.uni WAIT_LOOP_%=;\n\t" \
            "WAIT_DONE_%=:\n\t}" \
            :: "r"(_mbar), "r"(_parity) : "memory"); \
    } \
} while(0)

#if HAS_TCGEN05
#define TCGEN05_ALLOC(smem_result_addr, nCols) \
    asm volatile("tcgen05.alloc.cta_group::1.sync.aligned.shared::cta.b32 [%0], %1;" \
        :: "r"((uint32_t)(smem_result_addr)), "r"((uint32_t)(nCols)) : "memory")
#define TCGEN05_DEALLOC(tmem_addr, nCols) \
    asm volatile("tcgen05.dealloc.cta_group::1.sync.aligned.b32 %0, %1;" \
        :: "r"(tmem_addr), "r"((uint32_t)(nCols)))
#define TCGEN05_RELINQUISH_ALLOC_PERMIT() \
    asm volatile("tcgen05.relinquish_alloc_permit.cta_group::1.sync.aligned;")
#define TCGEN05_COMMIT(mbar_smem_addr) \
    asm volatile("tcgen05.commit.cta_group::1.mbarrier::arrive::one.shared::cluster.b64 [%0];" \
        :: "r"((uint32_t)(mbar_smem_addr)) : "memory")
#define TCGEN05_FENCE_BEFORE() asm volatile("tcgen05.fence::before_thread_sync;" ::: "memory")
#define TCGEN05_FENCE_AFTER()  asm volatile("tcgen05.fence::after_thread_sync;" ::: "memory")
#define TCGEN05_WAIT_LD()      asm volatile("tcgen05.wait::ld.sync.aligned;" ::: "memory")
#define TCGEN05_LD_32X32B_X32(r, tmem_addr) \
    asm volatile("tcgen05.ld.sync.aligned.32x32b.x32.b32 " \
        "{%0, %1, %2, %3, %4, %5, %6, %7, %8, %9, %10, %11, %12, %13, %14, %15, " \
        " %16, %17, %18, %19, %20, %21, %22, %23, %24, %25, %26, %27, %28, %29, %30, %31}, [%32];" \
        : "=r"((r)[0]),  "=r"((r)[1]),  "=r"((r)[2]),  "=r"((r)[3]), \
          "=r"((r)[4]),  "=r"((r)[5]),  "=r"((r)[6]),  "=r"((r)[7]), \
          "=r"((r)[8]),  "=r"((r)[9]),  "=r"((r)[10]), "=r"((r)[11]), \
          "=r"((r)[12]), "=r"((r)[13]), "=r"((r)[14]), "=r"((r)[15]), \
          "=r"((r)[16]), "=r"((r)[17]), "=r"((r)[18]), "=r"((r)[19]), \
          "=r"((r)[20]), "=r"((r)[21]), "=r"((r)[22]), "=r"((r)[23]), \
          "=r"((r)[24]), "=r"((r)[25]), "=r"((r)[26]), "=r"((r)[27]), \
          "=r"((r)[28]), "=r"((r)[29]), "=r"((r)[30]), "=r"((r)[31]) \
        : "r"(tmem_addr))
#define TMA_LOAD_3D(smem_addr, tensor_map, cx, cy, cz, mbar) \
    asm volatile("cp.async.bulk.tensor.3d.shared::cta.global.tile.mbarrier::complete_tx::bytes " \
        "[%0], [%1, {%2, %3, %4}], [%5];" \
        :: "r"((uint32_t)(smem_addr)), "l"(tensor_map), \
           "r"((int32_t)(cx)), "r"((int32_t)(cy)), "r"((int32_t)(cz)), \
           "r"((uint32_t)(mbar)) : "memory")

// SW64 smem descriptor (64-byte rows, BK=32 bf16):
// layout_type=4 (SW64), version=1, SBO=32 (8 rows x 64B = 512B), LBO=1.
static constexpr uint64_t SMEM_DESC_BASE_SW64 =
    (uint64_t(4)  << 61) | (uint64_t(1) << 46) | (uint64_t(32) << 32) | (uint64_t(1) << 16);
#define MAKE_SMEM_DESC(base_addr) \
    (SMEM_DESC_BASE_SW64 | ((uint64_t)((base_addr) >> 4) & 0x3FFF))

// SS-mode cg1 kind::f16 MMA (bf16 in, fp32 accum)
__device__ __forceinline__ void mma_f16_ss(uint32_t d_tmem, uint64_t a_desc,
                                           uint64_t b_desc, uint32_t idesc, bool acc)
{
    uint32_t en = acc ? 1u : 0u;
    asm volatile(
        "{\n\t.reg .pred p;\n\tsetp.ne.u32 p, %4, 0;\n\t"
        "tcgen05.mma.cta_group::1.kind::f16 [%0], %1, %2, %3, {%5, %5, %5, %5}, p;\n\t}"
        :: "r"(d_tmem), "l"(a_desc), "l"(b_desc), "r"(idesc), "r"(en), "r"(0u)
        : "memory");
}
#endif // HAS_TCGEN05

// idesc: F32 accum (1<<4), A=BF16 (1<<7), B=BF16 (1<<10), N=256, M=128
static constexpr uint32_t IDESC_BF16_128x256 =
    (1u << 4) | (1u << 7) | (1u << 10) | ((256u / 8u) << 17) | ((128u / 16u) << 24);

// ===================== smem layout (dynamic) =====================
static constexpr int OFF_TMEM  = 0;
static constexpr int OFF_FULLB = 8;                  // full[s] = 8 + 8s  (s<4)
static constexpr int OFF_DONEB = 40;                 // done[s] = 40 + 8s (s<4)
static constexpr int OFF_BIAS  = 128;                // 256 f32 -> [128,1152)
static constexpr int OFF_DATA  = 2048;
static constexpr int SMEM_BYTES = 198656;            // both configs fill this

__device__ __forceinline__ void split_store(float v, __nv_bfloat16* hi, __nv_bfloat16* lo)
{
    __nv_bfloat16 h = __float2bfloat16(v);
    *hi = h;
    *lo = __float2bfloat16(v - __bfloat162float(h));
}

// =====================================================================
// TMA-fed GEMM on pre-split bf16 planes: C[m][n] = sum_k A[m][k]*B[n][k]
// (3-term split-bf16). BK=32 (SW64), warp-specialized producer/consumer.
// M2=false: 128x256 tile, 4 stages x 48KB. M2=true: 256x256 tile (two
// 128x256 accumulators in TMEM cols [0,256) and [256,512)), 3 stages x 64KB.
// BIAS_MODE: 0=none, 1=bias[m], 2=bias[n]. OUT_BF16: write hi/lo planes.
// =====================================================================
template <int BIAS_MODE, bool OUT_BF16, bool M2>
__global__ __launch_bounds__(256, 1)
void tc_gemm_tma(const __grid_constant__ CUtensorMap mapAhi,
                 const __grid_constant__ CUtensorMap mapAlo,
                 const __grid_constant__ CUtensorMap mapBhi,
                 const __grid_constant__ CUtensorMap mapBlo,
                 const __nv_bfloat16* __restrict__ Ahi,   // raw planes (fallback only)
                 const __nv_bfloat16* __restrict__ Alo,
                 const __nv_bfloat16* __restrict__ Bhi,
                 const __nv_bfloat16* __restrict__ Blo,
                 const float* __restrict__ bias,
                 float* __restrict__ Cf,
                 __nv_bfloat16* __restrict__ Chi,
                 __nv_bfloat16* __restrict__ Clo,
                 int M, int Nn, int K, int ldc,
                 long long strideA, long long strideB, long long strideC,
                 int zA, int zB)
{
    constexpr int AROWS   = M2 ? 256 : 128;
    constexpr int NSTAGE  = M2 ? 3 : 4;
    constexpr int OFF_ALO = AROWS * 64;          // A plane = AROWS x 64B
    constexpr int OFF_BHI = AROWS * 128;
    constexpr int OFF_BLO = AROWS * 128 + 16384;
    constexpr int STAGE_STRIDE = AROWS * 128 + 32768;   // 64KB / 48KB
    constexpr uint32_t TX_BYTES = (uint32_t)STAGE_STRIDE;
    constexpr int TMEM_COLS = M2 ? 512 : 256;

    extern __shared__ char smem[];
    const int tid = threadIdx.x;
    const int n0 = blockIdx.x * 256;
    const int m0 = blockIdx.y * AROWS;

    if (Cf)  Cf  += strideC * blockIdx.z;
    if (Chi) { Chi += strideC * blockIdx.z; Clo += strideC * blockIdx.z; }

#if HAS_TCGEN05
    const uint32_t sb = smem_to_u32(smem);
    const int wid = tid >> 5;
    const int zcA = zA ? blockIdx.z : 0;
    const int zcB = zB ? blockIdx.z : 0;

    if (tid == 0) {
        #pragma unroll
        for (int s = 0; s < NSTAGE; s++) {
            MBARRIER_INIT(sb + OFF_FULLB + 8 * s, 1);
            MBARRIER_INIT(sb + OFF_DONEB + 8 * s, 1);
        }
    }
    if (wid == 0) {
        TCGEN05_ALLOC(sb + OFF_TMEM, TMEM_COLS);
        TCGEN05_RELINQUISH_ALLOC_PERMIT();
    }
    if (BIAS_MODE == 2) {
        int n = n0 + tid;
        *(float*)(smem + OFF_BIAS + tid * 4) = (n < Nn) ? bias[n] : 0.0f;
    }
    __syncthreads();

    uint32_t tmem;
    asm volatile("ld.shared.b32 %0, [%1];" : "=r"(tmem) : "r"(sb + OFF_TMEM));

    const int nc = K / 32;

    // ---- producer: warp 1 lane 0. Issues TMA; paced by done barriers. ----
    if (tid == 32) {
        int phD[NSTAGE] = {};
        auto issue = [&](int c) {
            const int st = c % NSTAGE;
            const uint32_t fb  = sb + OFF_FULLB + 8 * st;
            const uint32_t b32 = sb + OFF_DATA + st * STAGE_STRIDE;
            MBARRIER_EXPECT_TX(fb, TX_BYTES);
            const int kt = c * 32;
            TMA_LOAD_3D(b32,           &mapAhi, kt, m0, zcA, fb);
            TMA_LOAD_3D(b32 + OFF_ALO, &mapAlo, kt, m0, zcA, fb);
            TMA_LOAD_3D(b32 + OFF_BHI, &mapBhi, kt, n0, zcB, fb);
            TMA_LOAD_3D(b32 + OFF_BLO, &mapBlo, kt, n0, zcB, fb);
        };
        #pragma unroll
        for (int c = 0; c < NSTAGE; c++) issue(c);
        for (int c = NSTAGE; c < nc; c++) {
            const int st = c % NSTAGE;
            MBARRIER_WAIT_PARITY(sb + OFF_DONEB + 8 * st, phD[st]);
            phD[st] ^= 1;
            issue(c);
        }
        #pragma unroll
        for (int s = 0; s < NSTAGE; s++)
            MBARRIER_WAIT_PARITY(sb + OFF_DONEB + 8 * s, phD[s]);
    }

    // ---- consumer: warp 0 lane 0. Waits full; issues MMAs; commits. ----
    if (tid == 0) {
        int phF[NSTAGE] = {};
        for (int c = 0; c < nc; c++) {
            const int st = c % NSTAGE;
            const uint32_t fb = sb + OFF_FULLB + 8 * st;
            const uint32_t db = sb + OFF_DONEB + 8 * st;
            MBARRIER_WAIT_PARITY(fb, phF[st]);
            phF[st] ^= 1;

            const uint32_t b32 = sb + OFF_DATA + st * STAGE_STRIDE;
            const uint64_t dAh = MAKE_SMEM_DESC(b32);
            const uint64_t dAl = MAKE_SMEM_DESC(b32 + OFF_ALO);
            const uint64_t dBh = MAKE_SMEM_DESC(b32 + OFF_BHI);
            const uint64_t dBl = MAKE_SMEM_DESC(b32 + OFF_BLO);
            #pragma unroll
            for (int mh = 0; mh < (M2 ? 2 : 1); mh++) {
                const uint32_t dT = tmem + mh * 256;
                const uint64_t am = (uint64_t)(mh * 512);   // +128 rows x 64B = 8192B
                #pragma unroll
                for (int ks = 0; ks < 2; ks++) {
                    const uint64_t o = (uint64_t)(ks * 2);
                    mma_f16_ss(dT, dAh + am + o, dBh + o, IDESC_BF16_128x256,
                               !(c == 0 && ks == 0));
                    mma_f16_ss(dT, dAh + am + o, dBl + o, IDESC_BF16_128x256, true);
                    mma_f16_ss(dT, dAl + am + o, dBh + o, IDESC_BF16_128x256, true);
                }
            }
            TCGEN05_COMMIT(db);
        }
    }

    __syncthreads();       // producer's drain guarantees all MMAs complete
    TCGEN05_FENCE_AFTER();

    // ---- epilogue ----
    // M2: thread t -> row m0+t, TMEM lane t&127 at base tmem + (t>=128)*256.
    // else: threads 0..127 -> rows m0+t at tmem.
    if (M2 || tid < 128) {
        const int m = m0 + tid;
        const bool mok = (m < M);
        const uint32_t tb = tmem + (M2 ? ((tid >> 7) * 256) : 0);
        const float bm = (BIAS_MODE == 1 && mok) ? bias[m] : 0.0f;
        const float* bs = (const float*)(smem + OFF_BIAS);
        #pragma unroll
        for (int b = 0; b < 8; b++) {
            uint32_t r[32];
            TCGEN05_LD_32X32B_X32(r, tb + b * 32);
            TCGEN05_WAIT_LD();
            if (mok) {
                #pragma unroll
                for (int j = 0; j < 8; j++) {
                    const int nc2 = b * 32 + j * 4;
                    const int n = n0 + nc2;
                    if (n + 4 <= Nn) {
                        float v[4];
                        #pragma unroll
                        for (int e = 0; e < 4; e++) {
                            v[e] = __uint_as_float(r[j * 4 + e]);
                            if (BIAS_MODE == 1) v[e] += bm;
                            if (BIAS_MODE == 2) v[e] += bs[nc2 + e];
                        }
                        if (OUT_BF16) {
                            __nv_bfloat16 h[4], l[4];
                            #pragma unroll
                            for (int e = 0; e < 4; e++) {
                                h[e] = __float2bfloat16(v[e]);
                                l[e] = __float2bfloat16(v[e] - __bfloat162float(h[e]));
                            }
                            uint2 hp, lp;
                            memcpy(&hp.x, &h[0], 4); memcpy(&hp.y, &h[2], 4);
                            memcpy(&lp.x, &l[0], 4); memcpy(&lp.y, &l[2], 4);
                            *(uint2*)(Chi + (long long)m * ldc + n) = hp;
                            *(uint2*)(Clo + (long long)m * ldc + n) = lp;
                        } else {
                            float4 o; o.x = v[0]; o.y = v[1]; o.z = v[2]; o.w = v[3];
                            *(float4*)(Cf + (long long)m * ldc + n) = o;
                        }
                    }
                }
            }
        }
    }
    TCGEN05_FENCE_BEFORE();
    __syncthreads();
    if (tid == 0) {
        #pragma unroll
        for (int s = 0; s < NSTAGE; s++) {
            mbarrier_inval(sb + OFF_FULLB + 8 * s);
            mbarrier_inval(sb + OFF_DONEB + 8 * s);
        }
    }
    if (wid == 0) TCGEN05_DEALLOC(tmem, TMEM_COLS);

#else  // ===== SIMT fallback (plain sm_103 pass; never runs on GB300) =====
    Ahi += strideA * blockIdx.z;  Alo += strideA * blockIdx.z;
    Bhi += strideB * blockIdx.z;  Blo += strideB * blockIdx.z;
    for (int idx = tid; idx < AROWS * 256; idx += 256) {
        const int i = idx >> 8, j = idx & 255;
        const int m = m0 + i, n = n0 + j;
        if (m < M && n < Nn) {
            float acc = 0.f;
            for (int k = 0; k < K; k++) {
                float a = __bfloat162float(Ahi[(long long)m * K + k]) +
                          __bfloat162float(Alo[(long long)m * K + k]);
                float b = __bfloat162float(Bhi[(long long)n * K + k]) +
                          __bfloat162float(Blo[(long long)n * K + k]);
                acc += a * b;
            }
            if (BIAS_MODE == 1) acc += bias[m];
            if (BIAS_MODE == 2) acc += bias[n];
            if (OUT_BF16)
                split_store(acc, Chi + (long long)m * ldc + n, Clo + (long long)m * ldc + n);
            else
                Cf[(long long)m * ldc + n] = acc;
        }
    }
#endif
}

// ===================== transpose + split x: [n][c][hw] -> [n][hw][c] =====================
__global__ __launch_bounds__(256)
void transpose_split_x(const float* __restrict__ bf,
                       __nv_bfloat16* __restrict__ xhi,
                       __nv_bfloat16* __restrict__ xlo)
{
    __shared__ float t[64][65];
    const int n = blockIdx.z;
    const int hw0 = blockIdx.x * 64;
    const int c0 = blockIdx.y * 64;
    const int tid = threadIdx.x;

    const float* src = bf + (size_t)n * C_DIM * HW_DIM;
    {
        const int r  = tid >> 2;
        const int cb = (tid & 3) * 16;
        const float* p = src + (size_t)(c0 + r) * HW_DIM + hw0 + cb;
        #pragma unroll
        for (int i = 0; i < 4; i++) {
            float4 v = *(const float4*)(p + i * 4);
            t[r][cb + i * 4 + 0] = v.x;
            t[r][cb + i * 4 + 1] = v.y;
            t[r][cb + i * 4 + 2] = v.z;
            t[r][cb + i * 4 + 3] = v.w;
        }
    }
    __syncthreads();
    {
        const int sl   = tid >> 2;
        const int cseg = (tid & 3) * 16;
        __nv_bfloat16 h[16], l[16];
        #pragma unroll
        for (int j = 0; j < 16; j++) {
            const float v = t[cseg + j][sl];
            h[j] = __float2bfloat16(v);
            l[j] = __float2bfloat16(v - __bfloat162float(h[j]));
        }
        const size_t o = (size_t)n * HW_DIM * C_DIM +
                         (size_t)(hw0 + sl) * C_DIM + c0 + cseg;
        uint4 hv0, hv1, lv0, lv1;
        memcpy(&hv0, &h[0], 16); memcpy(&hv1, &h[8], 16);
        memcpy(&lv0, &l[0], 16); memcpy(&lv1, &l[8], 16);
        *(uint4*)(xhi + o)     = hv0;
        *(uint4*)(xhi + o + 8) = hv1;
        *(uint4*)(xlo + o)     = lv0;
        *(uint4*)(xlo + o + 8) = lv1;
    }
}

// ===================== split W (all three weights, one launch, vectorized) =====================
__global__ __launch_bounds__(256)
void split_w3(const float* __restrict__ Wq, const float* __restrict__ Wk,
              const float* __restrict__ Wv,
              __nv_bfloat16* __restrict__ whi, __nv_bfloat16* __restrict__ wlo)
{
    const int which = blockIdx.y;
    const float* W = (which == 0) ? Wq : (which == 1) ? Wk : Wv;
    const size_t base = (size_t)which * D_DIM * C_DIM;
    const int i4 = (blockIdx.x * 256 + threadIdx.x) * 4;
    if (i4 < D_DIM * C_DIM) {
        float4 v = *(const float4*)(W + i4);
        __nv_bfloat16 h[4], l[4];
        float f[4] = {v.x, v.y, v.z, v.w};
        #pragma unroll
        for (int e = 0; e < 4; e++) {
            h[e] = __float2bfloat16(f[e]);
            l[e] = __float2bfloat16(f[e] - __bfloat162float(h[e]));
        }
        uint2 hp, lp;
        memcpy(&hp, &h[0], 8);
        memcpy(&lp, &l[0], 8);
        *(uint2*)(whi + base + i4) = hp;
        *(uint2*)(wlo + base + i4) = lp;
    }
}

// ===================== softmax rows of 512 -> bf16 hi/lo planes =====================
__global__ __launch_bounds__(128)
void softmax_split(const float* __restrict__ S,
                   __nv_bfloat16* __restrict__ ahi, __nv_bfloat16* __restrict__ alo)
{
    const long long row = blockIdx.x;
    const float* p = S + row * D_DIM;
    const int t = threadIdx.x;

    float4 v = *(const float4*)(p + t * 4);
    float f[4] = {v.x, v.y, v.z, v.w};

    __shared__ float red_max[4];
    __shared__ float red_sum[4];

    float m = fmaxf(fmaxf(f[0], f[1]), fmaxf(f[2], f[3]));
    #pragma unroll
    for (int o = 16; o > 0; o >>= 1)
        m = fmaxf(m, __shfl_xor_sync(0xffffffffu, m, o));
    if ((t & 31) == 0) red_max[t >> 5] = m;
    __syncthreads();
    float rowmax = fmaxf(fmaxf(red_max[0], red_max[1]), fmaxf(red_max[2], red_max[3]));

    float e[4];
    #pragma unroll
    for (int i = 0; i < 4; i++) e[i] = __expf(f[i] - rowmax);
    float s = e[0] + e[1] + e[2] + e[3];
    #pragma unroll
    for (int o = 16; o > 0; o >>= 1)
        s += __shfl_xor_sync(0xffffffffu, s, o);
    if ((t & 31) == 0) red_sum[t >> 5] = s;
    __syncthreads();
    const float inv = 1.0f / (red_sum[0] + red_sum[1] + red_sum[2] + red_sum[3]);

    __nv_bfloat16 h[4], l[4];
    #pragma unroll
    for (int i = 0; i < 4; i++) {
        const float pv = e[i] * inv;
        h[i] = __float2bfloat16(pv);
        l[i] = __float2bfloat16(pv - __bfloat162float(h[i]));
    }
    uint2 hp, lp;
    memcpy(&hp, &h[0], 8);
    memcpy(&lp, &l[0], 8);
    *(uint2*)(ahi + row * D_DIM + t * 4) = hp;
    *(uint2*)(alo + row * D_DIM + t * 4) = lp;
}

// ===================== host: tensormap encode via driver entry point =====================
typedef CUresult (*EncodeTiledFn)(
    CUtensorMap*, CUtensorMapDataType, cuuint32_t, void*,
    const cuuint64_t*, const cuuint64_t*, const cuuint32_t*, const cuuint32_t*,
    CUtensorMapInterleave, CUtensorMapSwizzle, CUtensorMapL2promotion,
    CUtensorMapFloatOOBfill);

static EncodeTiledFn get_encode_fn()
{
    static EncodeTiledFn fn = nullptr;
    if (!fn) {
        cudaDriverEntryPointQueryResult st;
        void* p = nullptr;
        cudaGetDriverEntryPoint("cuTensorMapEncodeTiled", &p,
                                cudaEnableDefault, &st);
        fn = (EncodeTiledFn)p;
    }
    return fn;
}

// 3D bf16 map: dims [K elems, rows, batch]; box [32, boxRows, 1]; SWIZZLE_64B.
static void make_map(CUtensorMap* m, const void* base,
                     unsigned long long K, unsigned long long rows,
                     unsigned long long batch, unsigned boxRows)
{
    cuuint64_t dims[3]    = {K, rows, batch};
    cuuint64_t strides[2] = {K * 2ull, K * rows * 2ull};
    cuuint32_t box[3]     = {32u, boxRows, 1u};
    cuuint32_t es[3]      = {1u, 1u, 1u};
    get_encode_fn()(m, CU_TENSOR_MAP_DATA_TYPE_BFLOAT16, 3, (void*)base,
                    dims, strides, box, es,
                    CU_TENSOR_MAP_INTERLEAVE_NONE, CU_TENSOR_MAP_SWIZZLE_64B,
                    CU_TENSOR_MAP_L2_PROMOTION_L2_128B,
                    CU_TENSOR_MAP_FLOAT_OOB_FILL_NONE);
}

extern "C" void kernel_launch(void* const* d_in, const int* in_sizes, int n_in,
                              void* d_out, int out_size)
{
    (void)in_sizes; (void)n_in; (void)out_size;
    const float* bf = (const float*)d_in[0];  // [N, C, HW]
    const float* Wq = (const float*)d_in[1];  // [D, C]
    const float* bq = (const float*)d_in[2];  // [D]
    const float* Wk = (const float*)d_in[3];
    const float* bk = (const float*)d_in[4];
    const float* Wv = (const float*)d_in[5];
    const float* bv = (const float*)d_in[6];
    float* out = (float*)d_out;               // [N, D, HW]

    __nv_bfloat16 *xh, *xl, *wh, *wl, *qh, *ql, *kh, *kl, *vh, *vl, *ah, *al;
    float *Sp;
    cudaGetSymbolAddress((void**)&xh, g_xt_hi);
    cudaGetSymbolAddress((void**)&xl, g_xt_lo);
    cudaGetSymbolAddress((void**)&wh, g_w_hi);
    cudaGetSymbolAddress((void**)&wl, g_w_lo);
    cudaGetSymbolAddress((void**)&qh, g_q_hi);
    cudaGetSymbolAddress((void**)&ql, g_q_lo);
    cudaGetSymbolAddress((void**)&kh, g_k_hi);
    cudaGetSymbolAddress((void**)&kl, g_k_lo);
    cudaGetSymbolAddress((void**)&vh, g_v_hi);
    cudaGetSymbolAddress((void**)&vl, g_v_lo);
    cudaGetSymbolAddress((void**)&ah, g_att_hi);
    cudaGetSymbolAddress((void**)&al, g_att_lo);
    cudaGetSymbolAddress((void**)&Sp, g_S);

    cudaFuncSetAttribute(tc_gemm_tma<1, true, true>,
        cudaFuncAttributeMaxDynamicSharedMemorySize, SMEM_BYTES);
    cudaFuncSetAttribute(tc_gemm_tma<2, true, true>,
        cudaFuncAttributeMaxDynamicSharedMemorySize, SMEM_BYTES);
    cudaFuncSetAttribute(tc_gemm_tma<0, false, false>,
        cudaFuncAttributeMaxDynamicSharedMemorySize, SMEM_BYTES);
    cudaFuncSetAttribute(tc_gemm_tma<0, false, true>,
        cudaFuncAttributeMaxDynamicSharedMemorySize, SMEM_BYTES);

    const dim3 blk(256);
    const size_t WSZ = (size_t)D_DIM * C_DIM;
    const long long sX  = (long long)HW_DIM * C_DIM;
    const long long sQ  = (long long)D_DIM * HW_DIM;
    const long long sV  = (long long)HW_DIM * D_DIM;
    const long long sS  = (long long)D_DIM * D_DIM;

    // 0) splits/transposes
    transpose_split_x<<<dim3(HW_DIM / 64, C_DIM / 64, N_B), blk>>>(bf, xh, xl);
    split_w3<<<dim3((D_DIM * C_DIM / 4 + 255) / 256, 3), blk>>>(Wq, Wk, Wv, wh, wl);

    // tensormaps (A-side boxRows = 256 for M2 kernels, 128 for scores)
    CUtensorMap mWq_h, mWq_l, mWk_h, mWk_l, mWv_h, mWv_l;
    CUtensorMap mXa_h, mXa_l, mXb_h, mXb_l;
    CUtensorMap mQ_h, mQ_l, mK_h, mK_l;
    CUtensorMap mV_h, mV_l, mAtt_h, mAtt_l;
    make_map(&mWq_h, wh + 0 * WSZ, C_DIM, D_DIM, 1, 256);
    make_map(&mWq_l, wl + 0 * WSZ, C_DIM, D_DIM, 1, 256);
    make_map(&mWk_h, wh + 1 * WSZ, C_DIM, D_DIM, 1, 256);
    make_map(&mWk_l, wl + 1 * WSZ, C_DIM, D_DIM, 1, 256);
    make_map(&mWv_h, wh + 2 * WSZ, C_DIM, D_DIM, 1, 256);
    make_map(&mWv_l, wl + 2 * WSZ, C_DIM, D_DIM, 1, 256);
    make_map(&mXb_h, xh, C_DIM, HW_DIM, N_B, 256);      // B for Q/K proj
    make_map(&mXb_l, xl, C_DIM, HW_DIM, N_B, 256);
    make_map(&mXa_h, xh, C_DIM, HW_DIM, N_B, 256);      // A for V proj (M2)
    make_map(&mXa_l, xl, C_DIM, HW_DIM, N_B, 256);
    make_map(&mQ_h, qh, HW_DIM, D_DIM, N_B, 128);       // A for scores (M128)
    make_map(&mQ_l, ql, HW_DIM, D_DIM, N_B, 128);
    make_map(&mK_h, kh, HW_DIM, D_DIM, N_B, 256);       // B for scores
    make_map(&mK_l, kl, HW_DIM, D_DIM, N_B, 256);
    make_map(&mV_h, vh, D_DIM, HW_DIM, N_B, 256);       // B for out
    make_map(&mV_l, vl, D_DIM, HW_DIM, N_B, 256);
    make_map(&mAtt_h, ah, D_DIM, D_DIM, N_B, 256);      // A for out (M2)
    make_map(&mAtt_l, al, D_DIM, D_DIM, N_B, 256);

    // 1) Q/K proj: M=d(512), N=s(3136), K=c(512). 256x256 tiles.
    const dim3 g_qk((HW_DIM + 255) / 256, D_DIM / 256, N_B);      // (13, 2, 16)
    tc_gemm_tma<1, true, true><<<g_qk, blk, SMEM_BYTES>>>(
        mWq_h, mWq_l, mXb_h, mXb_l,
        wh + 0 * WSZ, wl + 0 * WSZ, xh, xl, bq, nullptr, qh, ql,
        D_DIM, HW_DIM, C_DIM, HW_DIM, 0, sX, sQ, 0, 1);
    tc_gemm_tma<1, true, true><<<g_qk, blk, SMEM_BYTES>>>(
        mWk_h, mWk_l, mXb_h, mXb_l,
        wh + 1 * WSZ, wl + 1 * WSZ, xh, xl, bk, nullptr, kh, kl,
        D_DIM, HW_DIM, C_DIM, HW_DIM, 0, sX, sQ, 0, 1);

    // 1b) V proj: M=s(3136), N=d(512), K=c(512). 256x256 tiles.
    const dim3 g_v(D_DIM / 256, (HW_DIM + 255) / 256, N_B);       // (2, 13, 16)
    tc_gemm_tma<2, true, true><<<g_v, blk, SMEM_BYTES>>>(
        mXa_h, mXa_l, mWv_h, mWv_l,
        xh, xl, wh + 2 * WSZ, wl + 2 * WSZ, bv, nullptr, vh, vl,
        HW_DIM, D_DIM, C_DIM, D_DIM, sX, 0, sV, 1, 0);

    // 2) scores: M=d, N=e, K=s(3136). 128x256 tiles (CTA count). Out fp32 S.
    const dim3 g_sc(D_DIM / 256, D_DIM / 128, N_B);               // (2, 4, 16)
    tc_gemm_tma<0, false, false><<<g_sc, blk, SMEM_BYTES>>>(
        mQ_h, mQ_l, mK_h, mK_l,
        qh, ql, kh, kl, nullptr, Sp, nullptr, nullptr,
        D_DIM, D_DIM, HW_DIM, D_DIM, sQ, sQ, sS, 1, 1);

    // 3) softmax -> att planes
    softmax_split<<<N_B * D_DIM, 128>>>(Sp, ah, al);

    // 4) out: M=d(512), N=s(3136), K=e(512). 256x256 tiles. Out fp32.
    const dim3 g_out((HW_DIM + 255) / 256, D_DIM / 256, N_B);     // (13, 2, 16)
    tc_gemm_tma<0, false, true><<<g_out, blk, SMEM_BYTES>>>(
        mAtt_h, mAtt_l, mV_h, mV_l,
        ah, al, vh, vl, nullptr, out, nullptr, nullptr,
        D_DIM, HW_DIM, D_DIM, HW_DIM, sS, sV, (long long)D_DIM * HW_DIM, 1, 1);
}

// round 16
// speedup vs baseline: 1.1110x; 1.0289x over previous
#include <cuda_runtime.h>
#include <cuda.h>
#include <cuda_bf16.h>
#include <cstdint>

#define N_B    16
#define C_DIM  512
#define HW_DIM 3136
#define D_DIM  512

// tcgen05 available only in the arch-specific (sm_103a/sm_100a) compile pass.
#if defined(__CUDA_ARCH_FEAT_SM103_ALL) || defined(__CUDA_ARCH_FEAT_SM100_ALL) || \
    (defined(__CUDA_ARCH_SPECIFIC__) && (__CUDA_ARCH_SPECIFIC__ == 1030 || __CUDA_ARCH_SPECIFIC__ == 1000))
#define HAS_TCGEN05 1
#else
#define HAS_TCGEN05 0
#endif

// ===================== scratch (__device__ globals; no allocs) =====================
__device__ __nv_bfloat16 g_xt_hi[(size_t)N_B * HW_DIM * C_DIM];  // [n][s][c]
__device__ __nv_bfloat16 g_xt_lo[(size_t)N_B * HW_DIM * C_DIM];
__device__ __nv_bfloat16 g_w_hi[3][(size_t)D_DIM * C_DIM];       // [qkv][d][c]
__device__ __nv_bfloat16 g_w_lo[3][(size_t)D_DIM * C_DIM];
__device__ __nv_bfloat16 g_q_hi[(size_t)N_B * D_DIM * HW_DIM];   // [n][d][s]
__device__ __nv_bfloat16 g_q_lo[(size_t)N_B * D_DIM * HW_DIM];
__device__ __nv_bfloat16 g_k_hi[(size_t)N_B * D_DIM * HW_DIM];   // [n][e][s]
__device__ __nv_bfloat16 g_k_lo[(size_t)N_B * D_DIM * HW_DIM];
__device__ __nv_bfloat16 g_v_hi[(size_t)N_B * HW_DIM * D_DIM];   // [n][s][d]
__device__ __nv_bfloat16 g_v_lo[(size_t)N_B * HW_DIM * D_DIM];
__device__ float         g_S[(size_t)N_B * D_DIM * D_DIM];       // [n][d][e]
__device__ __nv_bfloat16 g_att_hi[(size_t)N_B * D_DIM * D_DIM];  // [n][d][e]
__device__ __nv_bfloat16 g_att_lo[(size_t)N_B * D_DIM * D_DIM];

// ===================== PTX helpers =====================
__device__ __forceinline__ uint32_t smem_to_u32(const void* smem_ptr) {
    uint32_t addr;
    asm("{ .reg .u64 tmp; cvta.to.shared.u64 tmp, %1; cvt.u32.u64 %0, tmp; }"
        : "=r"(addr) : "l"(smem_ptr));
    return addr;
}
#define MBARRIER_INIT(mbar_smem_addr, count) \
    asm volatile("mbarrier.init.shared.b64 [%0], %1;" \
        :: "r"((uint32_t)(mbar_smem_addr)), "r"((uint32_t)(count)) : "memory")
#define MBARRIER_EXPECT_TX(mbar_smem_addr, tx_bytes) \
    asm volatile("mbarrier.arrive.expect_tx.shared.b64 _, [%0], %1;" \
        :: "r"((uint32_t)(mbar_smem_addr)), "r"((uint32_t)(tx_bytes)) : "memory")
__device__ __forceinline__ void mbarrier_inval(uint32_t mbar_smem_addr) {
    asm volatile("mbarrier.inval.shared.b64 [%0];" :: "r"(mbar_smem_addr) : "memory");
}
#define MBARRIER_WAIT_PARITY(mbar_smem_addr, phase_parity) do { \
    uint32_t _mbar = (uint32_t)(mbar_smem_addr); \
    uint32_t _parity = (uint32_t)(phase_parity); \
    uint32_t _done; \
    asm volatile("{\n\t.reg .pred p;\n\t" \
        "mbarrier.try_wait.parity.acquire.cta.shared::cta.b64 p, [%1], %2;\n\t" \
        "selp.b32 %0, 1, 0, p;\n\t}" \
        : "=r"(_done) : "r"(_mbar), "r"(_parity) : "memory"); \
    if (!_done) { \
        asm volatile("{\n\t.reg .pred P1;\n\t" \
            "WAIT_LOOP_%=:\n\t" \
            "mbarrier.try_wait.parity.acquire.cta.shared::cta.b64 P1, [%0], %1, 0x989680;\n\t" \
            "@P1 bra.uni WAIT_DONE_%=;\n\t" \
            "bra.uni WAIT_LOOP_%=;\n\t" \
            "WAIT_DONE_%=:\n\t}" \
            :: "r"(_mbar), "r"(_parity) : "memory"); \
    } \
} while(0)

#if HAS_TCGEN05
#define TCGEN05_ALLOC(smem_result_addr, nCols) \
    asm volatile("tcgen05.alloc.cta_group::1.sync.aligned.shared::cta.b32 [%0], %1;" \
        :: "r"((uint32_t)(smem_result_addr)), "r"((uint32_t)(nCols)) : "memory")
#define TCGEN05_DEALLOC(tmem_addr, nCols) \
    asm volatile("tcgen05.dealloc.cta_group::1.sync.aligned.b32 %0, %1;" \
        :: "r"(tmem_addr), "r"((uint32_t)(nCols)))
#define TCGEN05_RELINQUISH_ALLOC_PERMIT() \
    asm volatile("tcgen05.relinquish_alloc_permit.cta_group::1.sync.aligned;")
#define TCGEN05_COMMIT(mbar_smem_addr) \
    asm volatile("tcgen05.commit.cta_group::1.mbarrier::arrive::one.shared::cluster.b64 [%0];" \
        :: "r"((uint32_t)(mbar_smem_addr)) : "memory")
#define TCGEN05_FENCE_BEFORE() asm volatile("tcgen05.fence::before_thread_sync;" ::: "memory")
#define TCGEN05_FENCE_AFTER()  asm volatile("tcgen05.fence::after_thread_sync;" ::: "memory")
#define TCGEN05_WAIT_LD()      asm volatile("tcgen05.wait::ld.sync.aligned;" ::: "memory")
#define TCGEN05_LD_32X32B_X32(r, tmem_addr) \
    asm volatile("tcgen05.ld.sync.aligned.32x32b.x32.b32 " \
        "{%0, %1, %2, %3, %4, %5, %6, %7, %8, %9, %10, %11, %12, %13, %14, %15, " \
        " %16, %17, %18, %19, %20, %21, %22, %23, %24, %25, %26, %27, %28, %29, %30, %31}, [%32];" \
        : "=r"((r)[0]),  "=r"((r)[1]),  "=r"((r)[2]),  "=r"((r)[3]), \
          "=r"((r)[4]),  "=r"((r)[5]),  "=r"((r)[6]),  "=r"((r)[7]), \
          "=r"((r)[8]),  "=r"((r)[9]),  "=r"((r)[10]), "=r"((r)[11]), \
          "=r"((r)[12]), "=r"((r)[13]), "=r"((r)[14]), "=r"((r)[15]), \
          "=r"((r)[16]), "=r"((r)[17]), "=r"((r)[18]), "=r"((r)[19]), \
          "=r"((r)[20]), "=r"((r)[21]), "=r"((r)[22]), "=r"((r)[23]), \
          "=r"((r)[24]), "=r"((r)[25]), "=r"((r)[26]), "=r"((r)[27]), \
          "=r"((r)[28]), "=r"((r)[29]), "=r"((r)[30]), "=r"((r)[31]) \
        : "r"(tmem_addr))
#define TMA_LOAD_3D(smem_addr, tensor_map, cx, cy, cz, mbar) \
    asm volatile("cp.async.bulk.tensor.3d.shared::cta.global.tile.mbarrier::complete_tx::bytes " \
        "[%0], [%1, {%2, %3, %4}], [%5];" \
        :: "r"((uint32_t)(smem_addr)), "l"(tensor_map), \
           "r"((int32_t)(cx)), "r"((int32_t)(cy)), "r"((int32_t)(cz)), \
           "r"((uint32_t)(mbar)) : "memory")

// SW64 smem descriptor (64-byte rows, BK=32 bf16):
// layout_type=4 (SW64), version=1, SBO=32 (8 rows x 64B = 512B), LBO=1.
static constexpr uint64_t SMEM_DESC_BASE_SW64 =
    (uint64_t(4)  << 61) | (uint64_t(1) << 46) | (uint64_t(32) << 32) | (uint64_t(1) << 16);
#define MAKE_SMEM_DESC(base_addr) \
    (SMEM_DESC_BASE_SW64 | ((uint64_t)((base_addr) >> 4) & 0x3FFF))

// SS-mode cg1 kind::f16 MMA (bf16 in, fp32 accum)
__device__ __forceinline__ void mma_f16_ss(uint32_t d_tmem, uint64_t a_desc,
                                           uint64_t b_desc, uint32_t idesc, bool acc)
{
    uint32_t en = acc ? 1u : 0u;
    asm volatile(
        "{\n\t.reg .pred p;\n\tsetp.ne.u32 p, %4, 0;\n\t"
        "tcgen05.mma.cta_group::1.kind::f16 [%0], %1, %2, %3, {%5, %5, %5, %5}, p;\n\t}"
        :: "r"(d_tmem), "l"(a_desc), "l"(b_desc), "r"(idesc), "r"(en), "r"(0u)
        : "memory");
}
#endif // HAS_TCGEN05

// idesc: F32 accum (1<<4), A=BF16 (1<<7), B=BF16 (1<<10), N=256, M=128
static constexpr uint32_t IDESC_BF16_128x256 =
    (1u << 4) | (1u << 7) | (1u << 10) | ((256u / 8u) << 17) | ((128u / 16u) << 24);

// ===================== smem layout (dynamic) =====================
static constexpr int OFF_TMEM  = 0;
static constexpr int OFF_FULLB = 8;                  // full[s] = 8 + 8s  (s<4)
static constexpr int OFF_DONEB = 40;                 // done[s] = 40 + 8s (s<4)
static constexpr int OFF_BIAS  = 128;                // 256 f32
static constexpr int OFF_DATA  = 2048;
static constexpr int SMEM_BYTES = 198656;

__device__ __forceinline__ void split_store(float v, __nv_bfloat16* hi, __nv_bfloat16* lo)
{
    __nv_bfloat16 h = __float2bfloat16(v);
    *hi = h;
    *lo = __float2bfloat16(v - __bfloat162float(h));
}

// =====================================================================
// Generic TMA-fed GEMM (r13 config): 128x256 tile, BK=32 (SW64), 4 stages
// x 48KB, warp-specialized producer/consumer, 1 CTA/SM.
// BIAS_MODE: 0=none, 1=bias[m], 2=bias[n]. OUT_BF16: write hi/lo planes.
// =====================================================================
template <int BIAS_MODE, bool OUT_BF16>
__global__ __launch_bounds__(256, 1)
void tc_gemm_tma(const __grid_constant__ CUtensorMap mapAhi,
                 const __grid_constant__ CUtensorMap mapAlo,
                 const __grid_constant__ CUtensorMap mapBhi,
                 const __grid_constant__ CUtensorMap mapBlo,
                 const __nv_bfloat16* __restrict__ Ahi,   // fallback only
                 const __nv_bfloat16* __restrict__ Alo,
                 const __nv_bfloat16* __restrict__ Bhi,
                 const __nv_bfloat16* __restrict__ Blo,
                 const float* __restrict__ bias,
                 float* __restrict__ Cf,
                 __nv_bfloat16* __restrict__ Chi,
                 __nv_bfloat16* __restrict__ Clo,
                 int M, int Nn, int K, int ldc,
                 long long strideA, long long strideB, long long strideC,
                 int zA, int zB)
{
    constexpr int NSTAGE = 4;
    constexpr int OFF_ALO = 8192;
    constexpr int OFF_BHI = 16384;
    constexpr int OFF_BLO = 32768;
    constexpr int STAGE_STRIDE = 49152;
    constexpr uint32_t TX_BYTES = 49152;

    extern __shared__ char smem[];
    const int tid = threadIdx.x;
    const int n0 = blockIdx.x * 256;
    const int m0 = blockIdx.y * 128;

    if (Cf)  Cf  += strideC * blockIdx.z;
    if (Chi) { Chi += strideC * blockIdx.z; Clo += strideC * blockIdx.z; }

#if HAS_TCGEN05
    const uint32_t sb = smem_to_u32(smem);
    const int wid = tid >> 5;
    const int zcA = zA ? blockIdx.z : 0;
    const int zcB = zB ? blockIdx.z : 0;

    if (tid == 0) {
        #pragma unroll
        for (int s = 0; s < NSTAGE; s++) {
            MBARRIER_INIT(sb + OFF_FULLB + 8 * s, 1);
            MBARRIER_INIT(sb + OFF_DONEB + 8 * s, 1);
        }
    }
    if (wid == 0) {
        TCGEN05_ALLOC(sb + OFF_TMEM, 256);
        TCGEN05_RELINQUISH_ALLOC_PERMIT();
    }
    if (BIAS_MODE == 2) {
        int n = n0 + tid;
        *(float*)(smem + OFF_BIAS + tid * 4) = (n < Nn) ? bias[n] : 0.0f;
    }
    __syncthreads();

    uint32_t tmem;
    asm volatile("ld.shared.b32 %0, [%1];" : "=r"(tmem) : "r"(sb + OFF_TMEM));

    const int nc = K / 32;

    if (tid == 32) {
        int phD[NSTAGE] = {};
        auto issue = [&](int c) {
            const int st = c & (NSTAGE - 1);
            const uint32_t fb  = sb + OFF_FULLB + 8 * st;
            const uint32_t b32 = sb + OFF_DATA + st * STAGE_STRIDE;
            MBARRIER_EXPECT_TX(fb, TX_BYTES);
            const int kt = c * 32;
            TMA_LOAD_3D(b32,           &mapAhi, kt, m0, zcA, fb);
            TMA_LOAD_3D(b32 + OFF_ALO, &mapAlo, kt, m0, zcA, fb);
            TMA_LOAD_3D(b32 + OFF_BHI, &mapBhi, kt, n0, zcB, fb);
            TMA_LOAD_3D(b32 + OFF_BLO, &mapBlo, kt, n0, zcB, fb);
        };
        #pragma unroll
        for (int c = 0; c < NSTAGE; c++) issue(c);
        for (int c = NSTAGE; c < nc; c++) {
            const int st = c & (NSTAGE - 1);
            MBARRIER_WAIT_PARITY(sb + OFF_DONEB + 8 * st, phD[st]);
            phD[st] ^= 1;
            issue(c);
        }
        #pragma unroll
        for (int s = 0; s < NSTAGE; s++)
            MBARRIER_WAIT_PARITY(sb + OFF_DONEB + 8 * s, phD[s]);
    }

    if (tid == 0) {
        int phF[NSTAGE] = {};
        for (int c = 0; c < nc; c++) {
            const int st = c & (NSTAGE - 1);
            MBARRIER_WAIT_PARITY(sb + OFF_FULLB + 8 * st, phF[st]);
            phF[st] ^= 1;

            const uint32_t b32 = sb + OFF_DATA + st * STAGE_STRIDE;
            const uint64_t dAh = MAKE_SMEM_DESC(b32);
            const uint64_t dAl = MAKE_SMEM_DESC(b32 + OFF_ALO);
            const uint64_t dBh = MAKE_SMEM_DESC(b32 + OFF_BHI);
            const uint64_t dBl = MAKE_SMEM_DESC(b32 + OFF_BLO);
            #pragma unroll
            for (int ks = 0; ks < 2; ks++) {
                const uint64_t o = (uint64_t)(ks * 2);
                mma_f16_ss(tmem, dAh + o, dBh + o, IDESC_BF16_128x256,
                           !(c == 0 && ks == 0));
                mma_f16_ss(tmem, dAh + o, dBl + o, IDESC_BF16_128x256, true);
                mma_f16_ss(tmem, dAl + o, dBh + o, IDESC_BF16_128x256, true);
            }
            TCGEN05_COMMIT(sb + OFF_DONEB + 8 * st);
        }
    }

    __syncthreads();
    TCGEN05_FENCE_AFTER();

    if (tid < 128) {
        const int m = m0 + tid;
        const bool mok = (m < M);
        const float bm = (BIAS_MODE == 1 && mok) ? bias[m] : 0.0f;
        const float* bs = (const float*)(smem + OFF_BIAS);
        #pragma unroll
        for (int b = 0; b < 8; b++) {
            uint32_t r[32];
            TCGEN05_LD_32X32B_X32(r, tmem + b * 32);
            TCGEN05_WAIT_LD();
            if (mok) {
                #pragma unroll
                for (int j = 0; j < 8; j++) {
                    const int nc2 = b * 32 + j * 4;
                    const int n = n0 + nc2;
                    if (n + 4 <= Nn) {
                        float v[4];
                        #pragma unroll
                        for (int e = 0; e < 4; e++) {
                            v[e] = __uint_as_float(r[j * 4 + e]);
                            if (BIAS_MODE == 1) v[e] += bm;
                            if (BIAS_MODE == 2) v[e] += bs[nc2 + e];
                        }
                        if (OUT_BF16) {
                            __nv_bfloat16 h[4], l[4];
                            #pragma unroll
                            for (int e = 0; e < 4; e++) {
                                h[e] = __float2bfloat16(v[e]);
                                l[e] = __float2bfloat16(v[e] - __bfloat162float(h[e]));
                            }
                            uint2 hp, lp;
                            memcpy(&hp.x, &h[0], 4); memcpy(&hp.y, &h[2], 4);
                            memcpy(&lp.x, &l[0], 4); memcpy(&lp.y, &l[2], 4);
                            *(uint2*)(Chi + (long long)m * ldc + n) = hp;
                            *(uint2*)(Clo + (long long)m * ldc + n) = lp;
                        } else {
                            float4 o; o.x = v[0]; o.y = v[1]; o.z = v[2]; o.w = v[3];
                            *(float4*)(Cf + (long long)m * ldc + n) = o;
                        }
                    }
                }
            }
        }
    }
    TCGEN05_FENCE_BEFORE();
    __syncthreads();
    if (tid == 0) {
        #pragma unroll
        for (int s = 0; s < NSTAGE; s++) {
            mbarrier_inval(sb + OFF_FULLB + 8 * s);
            mbarrier_inval(sb + OFF_DONEB + 8 * s);
        }
    }
    if (wid == 0) TCGEN05_DEALLOC(tmem, 256);

#else
    Ahi += strideA * blockIdx.z;  Alo += strideA * blockIdx.z;
    Bhi += strideB * blockIdx.z;  Blo += strideB * blockIdx.z;
    for (int idx = tid; idx < 128 * 256; idx += 256) {
        const int i = idx >> 8, j = idx & 255;
        const int m = m0 + i, n = n0 + j;
        if (m < M && n < Nn) {
            float acc = 0.f;
            for (int k = 0; k < K; k++) {
                float a = __bfloat162float(Ahi[(long long)m * K + k]) +
                          __bfloat162float(Alo[(long long)m * K + k]);
                float b = __bfloat162float(Bhi[(long long)n * K + k]) +
                          __bfloat162float(Blo[(long long)n * K + k]);
                acc += a * b;
            }
            if (BIAS_MODE == 1) acc += bias[m];
            if (BIAS_MODE == 2) acc += bias[n];
            if (OUT_BF16)
                split_store(acc, Chi + (long long)m * ldc + n, Clo + (long long)m * ldc + n);
            else
                Cf[(long long)m * ldc + n] = acc;
        }
    }
#endif
}

// =====================================================================
// Fused Q+K projection: one CTA computes Q[m0:128,n0:256] and K[m0:128,
// n0:256] for the SAME shared B = xT tile. Two accumulators in TMEM cols
// [0,256) and [256,512). BK=32 (SW64), 3 stages x 64KB.
// =====================================================================
__global__ __launch_bounds__(256, 1)
void tc_gemm_qk(const __grid_constant__ CUtensorMap mapAqh,
                const __grid_constant__ CUtensorMap mapAql,
                const __grid_constant__ CUtensorMap mapAkh,
                const __grid_constant__ CUtensorMap mapAkl,
                const __grid_constant__ CUtensorMap mapBhi,
                const __grid_constant__ CUtensorMap mapBlo,
                const __nv_bfloat16* __restrict__ Wqh,    // fallback only
                const __nv_bfloat16* __restrict__ Wql,
                const __nv_bfloat16* __restrict__ Wkh,
                const __nv_bfloat16* __restrict__ Wkl,
                const __nv_bfloat16* __restrict__ Xh,
                const __nv_bfloat16* __restrict__ Xl,
                const float* __restrict__ bq,
                const float* __restrict__ bk,
                __nv_bfloat16* __restrict__ Qhi, __nv_bfloat16* __restrict__ Qlo,
                __nv_bfloat16* __restrict__ Khi, __nv_bfloat16* __restrict__ Klo,
                long long strideB, long long strideC)
{
    constexpr int NSTAGE = 3;
    constexpr int OFF_AQL = 8192;
    constexpr int OFF_AKH = 16384;
    constexpr int OFF_AKL = 24576;
    constexpr int OFF_BH  = 32768;
    constexpr int OFF_BL  = 49152;
    constexpr int STAGE_STRIDE = 65536;
    constexpr uint32_t TX_BYTES = 65536;

    extern __shared__ char smem[];
    const int tid = threadIdx.x;
    const int n0 = blockIdx.x * 256;
    const int m0 = blockIdx.y * 128;
    const int z  = blockIdx.z;

    Qhi += strideC * z; Qlo += strideC * z;
    Khi += strideC * z; Klo += strideC * z;

#if HAS_TCGEN05
    const uint32_t sb = smem_to_u32(smem);
    const int wid = tid >> 5;

    if (tid == 0) {
        #pragma unroll
        for (int s = 0; s < NSTAGE; s++) {
            MBARRIER_INIT(sb + OFF_FULLB + 8 * s, 1);
            MBARRIER_INIT(sb + OFF_DONEB + 8 * s, 1);
        }
    }
    if (wid == 0) {
        TCGEN05_ALLOC(sb + OFF_TMEM, 512);
        TCGEN05_RELINQUISH_ALLOC_PERMIT();
    }
    __syncthreads();

    uint32_t tmem;
    asm volatile("ld.shared.b32 %0, [%1];" : "=r"(tmem) : "r"(sb + OFF_TMEM));

    const int nc = C_DIM / 32;   // 16

    if (tid == 32) {
        int phD[NSTAGE] = {};
        auto issue = [&](int c) {
            const int st = c % NSTAGE;
            const uint32_t fb  = sb + OFF_FULLB + 8 * st;
            const uint32_t b32 = sb + OFF_DATA + st * STAGE_STRIDE;
            MBARRIER_EXPECT_TX(fb, TX_BYTES);
            const int kt = c * 32;
            TMA_LOAD_3D(b32,           &mapAqh, kt, m0, 0, fb);
            TMA_LOAD_3D(b32 + OFF_AQL, &mapAql, kt, m0, 0, fb);
            TMA_LOAD_3D(b32 + OFF_AKH, &mapAkh, kt, m0, 0, fb);
            TMA_LOAD_3D(b32 + OFF_AKL, &mapAkl, kt, m0, 0, fb);
            TMA_LOAD_3D(b32 + OFF_BH,  &mapBhi, kt, n0, z, fb);
            TMA_LOAD_3D(b32 + OFF_BL,  &mapBlo, kt, n0, z, fb);
        };
        #pragma unroll
        for (int c = 0; c < NSTAGE; c++) issue(c);
        for (int c = NSTAGE; c < nc; c++) {
            const int st = c % NSTAGE;
            MBARRIER_WAIT_PARITY(sb + OFF_DONEB + 8 * st, phD[st]);
            phD[st] ^= 1;
            issue(c);
        }
        #pragma unroll
        for (int s = 0; s < NSTAGE; s++)
            MBARRIER_WAIT_PARITY(sb + OFF_DONEB + 8 * s, phD[s]);
    }

    if (tid == 0) {
        int phF[NSTAGE] = {};
        for (int c = 0; c < nc; c++) {
            const int st = c % NSTAGE;
            MBARRIER_WAIT_PARITY(sb + OFF_FULLB + 8 * st, phF[st]);
            phF[st] ^= 1;

            const uint32_t b32 = sb + OFF_DATA + st * STAGE_STRIDE;
            const uint64_t dQh = MAKE_SMEM_DESC(b32);
            const uint64_t dQl = MAKE_SMEM_DESC(b32 + OFF_AQL);
            const uint64_t dKh = MAKE_SMEM_DESC(b32 + OFF_AKH);
            const uint64_t dKl = MAKE_SMEM_DESC(b32 + OFF_AKL);
            const uint64_t dBh = MAKE_SMEM_DESC(b32 + OFF_BH);
            const uint64_t dBl = MAKE_SMEM_DESC(b32 + OFF_BL);
            #pragma unroll
            for (int ks = 0; ks < 2; ks++) {
                const uint64_t o = (uint64_t)(ks * 2);
                const bool first = (c == 0 && ks == 0);
                mma_f16_ss(tmem,       dQh + o, dBh + o, IDESC_BF16_128x256, !first);
                mma_f16_ss(tmem,       dQh + o, dBl + o, IDESC_BF16_128x256, true);
                mma_f16_ss(tmem,       dQl + o, dBh + o, IDESC_BF16_128x256, true);
                mma_f16_ss(tmem + 256, dKh + o, dBh + o, IDESC_BF16_128x256, !first);
                mma_f16_ss(tmem + 256, dKh + o, dBl + o, IDESC_BF16_128x256, true);
                mma_f16_ss(tmem + 256, dKl + o, dBh + o, IDESC_BF16_128x256, true);
            }
            TCGEN05_COMMIT(sb + OFF_DONEB + 8 * st);
        }
    }

    __syncthreads();
    TCGEN05_FENCE_AFTER();

    // epilogue: threads 0..127 -> Q rows; 128..255 -> K rows (same m).
    {
        const int half = tid >> 7;
        const int m = m0 + (tid & 127);
        const uint32_t tb = tmem + half * 256;
        const float bm = half ? bk[m] : bq[m];
        __nv_bfloat16* Chi = half ? Khi : Qhi;
        __nv_bfloat16* Clo = half ? Klo : Qlo;
        #pragma unroll
        for (int b = 0; b < 8; b++) {
            uint32_t r[32];
            TCGEN05_LD_32X32B_X32(r, tb + b * 32);
            TCGEN05_WAIT_LD();
            #pragma unroll
            for (int j = 0; j < 8; j++) {
                const int nc2 = b * 32 + j * 4;
                const int n = n0 + nc2;
                if (n + 4 <= HW_DIM) {
                    __nv_bfloat16 h[4], l[4];
                    #pragma unroll
                    for (int e = 0; e < 4; e++) {
                        const float v = __uint_as_float(r[j * 4 + e]) + bm;
                        h[e] = __float2bfloat16(v);
                        l[e] = __float2bfloat16(v - __bfloat162float(h[e]));
                    }
                    uint2 hp, lp;
                    memcpy(&hp.x, &h[0], 4); memcpy(&hp.y, &h[2], 4);
                    memcpy(&lp.x, &l[0], 4); memcpy(&lp.y, &l[2], 4);
                    *(uint2*)(Chi + (long long)m * HW_DIM + n) = hp;
                    *(uint2*)(Clo + (long long)m * HW_DIM + n) = lp;
                }
            }
        }
    }
    TCGEN05_FENCE_BEFORE();
    __syncthreads();
    if (tid == 0) {
        #pragma unroll
        for (int s = 0; s < NSTAGE; s++) {
            mbarrier_inval(sb + OFF_FULLB + 8 * s);
            mbarrier_inval(sb + OFF_DONEB + 8 * s);
        }
    }
    if (wid == 0) TCGEN05_DEALLOC(tmem, 512);

#else   // SIMT fallback
    const __nv_bfloat16* Xhz = Xh + strideB * z;
    const __nv_bfloat16* Xlz = Xl + strideB * z;
    for (int idx = tid; idx < 128 * 256; idx += 256) {
        const int i = idx >> 8, j = idx & 255;
        const int m = m0 + i, n = n0 + j;
        if (n < HW_DIM) {
            float aq = 0.f, ak = 0.f;
            for (int k = 0; k < C_DIM; k++) {
                float b = __bfloat162float(Xhz[(long long)n * C_DIM + k]) +
                          __bfloat162float(Xlz[(long long)n * C_DIM + k]);
                aq += (__bfloat162float(Wqh[(long long)m * C_DIM + k]) +
                       __bfloat162float(Wql[(long long)m * C_DIM + k])) * b;
                ak += (__bfloat162float(Wkh[(long long)m * C_DIM + k]) +
                       __bfloat162float(Wkl[(long long)m * C_DIM + k])) * b;
            }
            split_store(aq + bq[m], Qhi + (long long)m * HW_DIM + n,
                                    Qlo + (long long)m * HW_DIM + n);
            split_store(ak + bk[m], Khi + (long long)m * HW_DIM + n,
                                    Klo + (long long)m * HW_DIM + n);
        }
    }
#endif
}

// ===================== transpose + split x: [n][c][hw] -> [n][hw][c] =====================
__global__ __launch_bounds__(256)
void transpose_split_x(const float* __restrict__ bf,
                       __nv_bfloat16* __restrict__ xhi,
                       __nv_bfloat16* __restrict__ xlo)
{
    __shared__ float t[64][65];
    const int n = blockIdx.z;
    const int hw0 = blockIdx.x * 64;
    const int c0 = blockIdx.y * 64;
    const int tid = threadIdx.x;

    const float* src = bf + (size_t)n * C_DIM * HW_DIM;
    {
        const int r  = tid >> 2;
        const int cb = (tid & 3) * 16;
        const float* p = src + (size_t)(c0 + r) * HW_DIM + hw0 + cb;
        #pragma unroll
        for (int i = 0; i < 4; i++) {
            float4 v = *(const float4*)(p + i * 4);
            t[r][cb + i * 4 + 0] = v.x;
            t[r][cb + i * 4 + 1] = v.y;
            t[r][cb + i * 4 + 2] = v.z;
            t[r][cb + i * 4 + 3] = v.w;
        }
    }
    __syncthreads();
    {
        const int sl   = tid >> 2;
        const int cseg = (tid & 3) * 16;
        __nv_bfloat16 h[16], l[16];
        #pragma unroll
        for (int j = 0; j < 16; j++) {
            const float v = t[cseg + j][sl];
            h[j] = __float2bfloat16(v);
            l[j] = __float2bfloat16(v - __bfloat162float(h[j]));
        }
        const size_t o = (size_t)n * HW_DIM * C_DIM +
                         (size_t)(hw0 + sl) * C_DIM + c0 + cseg;
        uint4 hv0, hv1, lv0, lv1;
        memcpy(&hv0, &h[0], 16); memcpy(&hv1, &h[8], 16);
        memcpy(&lv0, &l[0], 16); memcpy(&lv1, &l[8], 16);
        *(uint4*)(xhi + o)     = hv0;
        *(uint4*)(xhi + o + 8) = hv1;
        *(uint4*)(xlo + o)     = lv0;
        *(uint4*)(xlo + o + 8) = lv1;
    }
}

// ===================== split W (all three weights, one launch, vectorized) =====================
__global__ __launch_bounds__(256)
void split_w3(const float* __restrict__ Wq, const float* __restrict__ Wk,
              const float* __restrict__ Wv,
              __nv_bfloat16* __restrict__ whi, __nv_bfloat16* __restrict__ wlo)
{
    const int which = blockIdx.y;
    const float* W = (which == 0) ? Wq : (which == 1) ? Wk : Wv;
    const size_t base = (size_t)which * D_DIM * C_DIM;
    const int i4 = (blockIdx.x * 256 + threadIdx.x) * 4;
    if (i4 < D_DIM * C_DIM) {
        float4 v = *(const float4*)(W + i4);
        __nv_bfloat16 h[4], l[4];
        float f[4] = {v.x, v.y, v.z, v.w};
        #pragma unroll
        for (int e = 0; e < 4; e++) {
            h[e] = __float2bfloat16(f[e]);
            l[e] = __float2bfloat16(f[e] - __bfloat162float(h[e]));
        }
        uint2 hp, lp;
        memcpy(&hp, &h[0], 8);
        memcpy(&lp, &l[0], 8);
        *(uint2*)(whi + base + i4) = hp;
        *(uint2*)(wlo + base + i4) = lp;
    }
}

// ===================== softmax rows of 512 -> bf16 hi/lo planes =====================
__global__ __launch_bounds__(128)
void softmax_split(const float* __restrict__ S,
                   __nv_bfloat16* __restrict__ ahi, __nv_bfloat16* __restrict__ alo)
{
    const long long row = blockIdx.x;
    const float* p = S + row * D_DIM;
    const int t = threadIdx.x;

    float4 v = *(const float4*)(p + t * 4);
    float f[4] = {v.x, v.y, v.z, v.w};

    __shared__ float red_max[4];
    __shared__ float red_sum[4];

    float m = fmaxf(fmaxf(f[0], f[1]), fmaxf(f[2], f[3]));
    #pragma unroll
    for (int o = 16; o > 0; o >>= 1)
        m = fmaxf(m, __shfl_xor_sync(0xffffffffu, m, o));
    if ((t & 31) == 0) red_max[t >> 5] = m;
    __syncthreads();
    float rowmax = fmaxf(fmaxf(red_max[0], red_max[1]), fmaxf(red_max[2], red_max[3]));

    float e[4];
    #pragma unroll
    for (int i = 0; i < 4; i++) e[i] = __expf(f[i] - rowmax);
    float s = e[0] + e[1] + e[2] + e[3];
    #pragma unroll
    for (int o = 16; o > 0; o >>= 1)
        s += __shfl_xor_sync(0xffffffffu, s, o);
    if ((t & 31) == 0) red_sum[t >> 5] = s;
    __syncthreads();
    const float inv = 1.0f / (red_sum[0] + red_sum[1] + red_sum[2] + red_sum[3]);

    __nv_bfloat16 h[4], l[4];
    #pragma unroll
    for (int i = 0; i < 4; i++) {
        const float pv = e[i] * inv;
        h[i] = __float2bfloat16(pv);
        l[i] = __float2bfloat16(pv - __bfloat162float(h[i]));
    }
    uint2 hp, lp;
    memcpy(&hp, &h[0], 8);
    memcpy(&lp, &l[0], 8);
    *(uint2*)(ahi + row * D_DIM + t * 4) = hp;
    *(uint2*)(alo + row * D_DIM + t * 4) = lp;
}

// ===================== host: tensormap encode via driver entry point =====================
typedef CUresult (*EncodeTiledFn)(
    CUtensorMap*, CUtensorMapDataType, cuuint32_t, void*,
    const cuuint64_t*, const cuuint64_t*, const cuuint32_t*, const cuuint32_t*,
    CUtensorMapInterleave, CUtensorMapSwizzle, CUtensorMapL2promotion,
    CUtensorMapFloatOOBfill);

static EncodeTiledFn get_encode_fn()
{
    static EncodeTiledFn fn = nullptr;
    if (!fn) {
        cudaDriverEntryPointQueryResult st;
        void* p = nullptr;
        cudaGetDriverEntryPoint("cuTensorMapEncodeTiled", &p,
                                cudaEnableDefault, &st);
        fn = (EncodeTiledFn)p;
    }
    return fn;
}

// 3D bf16 map: dims [K elems, rows, batch]; box [32, boxRows, 1]; SWIZZLE_64B.
static void make_map(CUtensorMap* m, const void* base,
                     unsigned long long K, unsigned long long rows,
                     unsigned long long batch, unsigned boxRows)
{
    cuuint64_t dims[3]    = {K, rows, batch};
    cuuint64_t strides[2] = {K * 2ull, K * rows * 2ull};
    cuuint32_t box[3]     = {32u, boxRows, 1u};
    cuuint32_t es[3]      = {1u, 1u, 1u};
    get_encode_fn()(m, CU_TENSOR_MAP_DATA_TYPE_BFLOAT16, 3, (void*)base,
                    dims, strides, box, es,
                    CU_TENSOR_MAP_INTERLEAVE_NONE, CU_TENSOR_MAP_SWIZZLE_64B,
                    CU_TENSOR_MAP_L2_PROMOTION_L2_128B,
                    CU_TENSOR_MAP_FLOAT_OOB_FILL_NONE);
}

extern "C" void kernel_launch(void* const* d_in, const int* in_sizes, int n_in,
                              void* d_out, int out_size)
{
    (void)in_sizes; (void)n_in; (void)out_size;
    const float* bf = (const float*)d_in[0];  // [N, C, HW]
    const float* Wq = (const float*)d_in[1];  // [D, C]
    const float* bq = (const float*)d_in[2];  // [D]
    const float* Wk = (const float*)d_in[3];
    const float* bk = (const float*)d_in[4];
    const float* Wv = (const float*)d_in[5];
    const float* bv = (const float*)d_in[6];
    float* out = (float*)d_out;               // [N, D, HW]

    __nv_bfloat16 *xh, *xl, *wh, *wl, *qh, *ql, *kh, *kl, *vh, *vl, *ah, *al;
    float *Sp;
    cudaGetSymbolAddress((void**)&xh, g_xt_hi);
    cudaGetSymbolAddress((void**)&xl, g_xt_lo);
    cudaGetSymbolAddress((void**)&wh, g_w_hi);
    cudaGetSymbolAddress((void**)&wl, g_w_lo);
    cudaGetSymbolAddress((void**)&qh, g_q_hi);
    cudaGetSymbolAddress((void**)&ql, g_q_lo);
    cudaGetSymbolAddress((void**)&kh, g_k_hi);
    cudaGetSymbolAddress((void**)&kl, g_k_lo);
    cudaGetSymbolAddress((void**)&vh, g_v_hi);
    cudaGetSymbolAddress((void**)&vl, g_v_lo);
    cudaGetSymbolAddress((void**)&ah, g_att_hi);
    cudaGetSymbolAddress((void**)&al, g_att_lo);
    cudaGetSymbolAddress((void**)&Sp, g_S);

    cudaFuncSetAttribute(tc_gemm_qk,
        cudaFuncAttributeMaxDynamicSharedMemorySize, SMEM_BYTES);
    cudaFuncSetAttribute(tc_gemm_tma<2, true>,
        cudaFuncAttributeMaxDynamicSharedMemorySize, SMEM_BYTES);
    cudaFuncSetAttribute(tc_gemm_tma<0, false>,
        cudaFuncAttributeMaxDynamicSharedMemorySize, SMEM_BYTES);

    const dim3 blk(256);
    const size_t WSZ = (size_t)D_DIM * C_DIM;
    const long long sX  = (long long)HW_DIM * C_DIM;
    const long long sQ  = (long long)D_DIM * HW_DIM;
    const long long sV  = (long long)HW_DIM * D_DIM;
    const long long sS  = (long long)D_DIM * D_DIM;

    // 0) splits/transposes
    transpose_split_x<<<dim3(HW_DIM / 64, C_DIM / 64, N_B), blk>>>(bf, xh, xl);
    split_w3<<<dim3((D_DIM * C_DIM / 4 + 255) / 256, 3), blk>>>(Wq, Wk, Wv, wh, wl);

    // tensormaps
    CUtensorMap mWq_h, mWq_l, mWk_h, mWk_l, mWv_h, mWv_l;
    CUtensorMap mXa_h, mXa_l, mXb_h, mXb_l;
    CUtensorMap mQ_h, mQ_l, mK_h, mK_l;
    CUtensorMap mV_h, mV_l, mAtt_h, mAtt_l;
    make_map(&mWq_h, wh + 0 * WSZ, C_DIM, D_DIM, 1, 128);
    make_map(&mWq_l, wl + 0 * WSZ, C_DIM, D_DIM, 1, 128);
    make_map(&mWk_h, wh + 1 * WSZ, C_DIM, D_DIM, 1, 128);
    make_map(&mWk_l, wl + 1 * WSZ, C_DIM, D_DIM, 1, 128);
    make_map(&mWv_h, wh + 2 * WSZ, C_DIM, D_DIM, 1, 256);
    make_map(&mWv_l, wl + 2 * WSZ, C_DIM, D_DIM, 1, 256);
    make_map(&mXb_h, xh, C_DIM, HW_DIM, N_B, 256);      // B for Q/K proj
    make_map(&mXb_l, xl, C_DIM, HW_DIM, N_B, 256);
    make_map(&mXa_h, xh, C_DIM, HW_DIM, N_B, 128);      // A for V proj
    make_map(&mXa_l, xl, C_DIM, HW_DIM, N_B, 128);
    make_map(&mQ_h, qh, HW_DIM, D_DIM, N_B, 128);
    make_map(&mQ_l, ql, HW_DIM, D_DIM, N_B, 128);
    make_map(&mK_h, kh, HW_DIM, D_DIM, N_B, 256);
    make_map(&mK_l, kl, HW_DIM, D_DIM, N_B, 256);
    make_map(&mV_h, vh, D_DIM, HW_DIM, N_B, 256);
    make_map(&mV_l, vl, D_DIM, HW_DIM, N_B, 256);
    make_map(&mAtt_h, ah, D_DIM, D_DIM, N_B, 128);
    make_map(&mAtt_l, al, D_DIM, D_DIM, N_B, 128);

    // 1) Fused Q+K proj: M=d(512), N=s(3136), K=c(512). Shared B tile.
    const dim3 g_qk((HW_DIM + 255) / 256, D_DIM / 128, N_B);      // (13, 4, 16)
    tc_gemm_qk<<<g_qk, blk, SMEM_BYTES>>>(
        mWq_h, mWq_l, mWk_h, mWk_l, mXb_h, mXb_l,
        wh + 0 * WSZ, wl + 0 * WSZ, wh + 1 * WSZ, wl + 1 * WSZ, xh, xl,
        bq, bk, qh, ql, kh, kl, sX, sQ);

    // 1b) V proj: M=s(3136), N=d(512), K=c(512). A=xT, B=Wv. 128x256 tiles.
    const dim3 g_v(D_DIM / 256, (HW_DIM + 127) / 128, N_B);       // (2, 25, 16)
    tc_gemm_tma<2, true><<<g_v, blk, SMEM_BYTES>>>(
        mXa_h, mXa_l, mWv_h, mWv_l,
        xh, xl, wh + 2 * WSZ, wl + 2 * WSZ, bv, nullptr, vh, vl,
        HW_DIM, D_DIM, C_DIM, D_DIM, sX, 0, sV, 1, 0);

    // 2) scores: M=d, N=e, K=s(3136). Out fp32 S.
    const dim3 g_sc(D_DIM / 256, D_DIM / 128, N_B);               // (2, 4, 16)
    tc_gemm_tma<0, false><<<g_sc, blk, SMEM_BYTES>>>(
        mQ_h, mQ_l, mK_h, mK_l,
        qh, ql, kh, kl, nullptr, Sp, nullptr, nullptr,
        D_DIM, D_DIM, HW_DIM, D_DIM, sQ, sQ, sS, 1, 1);

    // 3) softmax -> att planes
    softmax_split<<<N_B * D_DIM, 128>>>(Sp, ah, al);

    // 4) out: M=d, N=s(3136), K=e(512). Out fp32.
    const dim3 g_out((HW_DIM + 255) / 256, D_DIM / 128, N_B);     // (13, 4, 16)
    tc_gemm_tma<0, false><<<g_out, blk, SMEM_BYTES>>>(
        mAtt_h, mAtt_l, mV_h, mV_l,
        ah, al, vh, vl, nullptr, out, nullptr, nullptr,
        D_DIM, HW_DIM, D_DIM, HW_DIM, sS, sV, (long long)D_DIM * HW_DIM, 1, 1);
}

// round 17
// speedup vs baseline: 1.7089x; 1.5382x over previous
#include <cuda_runtime.h>
#include <cuda.h>
#include <cuda_bf16.h>
#include <cstdint>

#define N_B    16
#define C_DIM  512
#define HW_DIM 3136
#define D_DIM  512

#if defined(__CUDA_ARCH_FEAT_SM103_ALL) || defined(__CUDA_ARCH_FEAT_SM100_ALL) || \
    (defined(__CUDA_ARCH_SPECIFIC__) && (__CUDA_ARCH_SPECIFIC__ == 1030 || __CUDA_ARCH_SPECIFIC__ == 1000))
#define HAS_TCGEN05 1
#else
#define HAS_TCGEN05 0
#endif

// ===================== scratch (__device__ globals; no allocs) =====================
__device__ __nv_bfloat16 g_xt_hi[(size_t)N_B * HW_DIM * C_DIM];  // [n][s][c]
__device__ __nv_bfloat16 g_xt_lo[(size_t)N_B * HW_DIM * C_DIM];
__device__ __nv_bfloat16 g_xs_hi[(size_t)N_B * C_DIM * HW_DIM];  // [n][c][s]
__device__ __nv_bfloat16 g_xs_lo[(size_t)N_B * C_DIM * HW_DIM];
__device__ __nv_bfloat16 g_w_hi[3][(size_t)D_DIM * C_DIM];       // [qkv][d][c]
__device__ __nv_bfloat16 g_w_lo[3][(size_t)D_DIM * C_DIM];
__device__ __nv_bfloat16 g_v_hi[(size_t)N_B * HW_DIM * D_DIM];   // [n][s][d]
__device__ __nv_bfloat16 g_v_lo[(size_t)N_B * HW_DIM * D_DIM];
__device__ float         g_G[(size_t)N_B * C_DIM * C_DIM];       // [n][c][c']
__device__ __nv_bfloat16 g_g_hi[(size_t)N_B * C_DIM * C_DIM];    // split G
__device__ __nv_bfloat16 g_g_lo[(size_t)N_B * C_DIM * C_DIM];
__device__ __nv_bfloat16 g_t1_hi[(size_t)N_B * D_DIM * C_DIM];   // Wq*G
__device__ __nv_bfloat16 g_t1_lo[(size_t)N_B * D_DIM * C_DIM];
__device__ float         g_S[(size_t)N_B * D_DIM * D_DIM];       // [n][d][e]
__device__ __nv_bfloat16 g_att_hi[(size_t)N_B * D_DIM * D_DIM];  // [n][d][e]
__device__ __nv_bfloat16 g_att_lo[(size_t)N_B * D_DIM * D_DIM];
__device__ float         g_sx[(size_t)N_B * C_DIM];              // sum_s x[c][s]
__device__ float         g_u[(size_t)N_B * D_DIM];               // Wq*sx
__device__ float         g_vv[(size_t)N_B * D_DIM];              // Wk*sx

// ===================== PTX helpers =====================
__device__ __forceinline__ uint32_t smem_to_u32(const void* smem_ptr) {
    uint32_t addr;
    asm("{ .reg .u64 tmp; cvta.to.shared.u64 tmp, %1; cvt.u32.u64 %0, tmp; }"
        : "=r"(addr) : "l"(smem_ptr));
    return addr;
}
#define MBARRIER_INIT(mbar_smem_addr, count) \
    asm volatile("mbarrier.init.shared.b64 [%0], %1;" \
        :: "r"((uint32_t)(mbar_smem_addr)), "r"((uint32_t)(count)) : "memory")
#define MBARRIER_EXPECT_TX(mbar_smem_addr, tx_bytes) \
    asm volatile("mbarrier.arrive.expect_tx.shared.b64 _, [%0], %1;" \
        :: "r"((uint32_t)(mbar_smem_addr)), "r"((uint32_t)(tx_bytes)) : "memory")
__device__ __forceinline__ void mbarrier_inval(uint32_t mbar_smem_addr) {
    asm volatile("mbarrier.inval.shared.b64 [%0];" :: "r"(mbar_smem_addr) : "memory");
}
#define MBARRIER_WAIT_PARITY(mbar_smem_addr, phase_parity) do { \
    uint32_t _mbar = (uint32_t)(mbar_smem_addr); \
    uint32_t _parity = (uint32_t)(phase_parity); \
    uint32_t _done; \
    asm volatile("{\n\t.reg .pred p;\n\t" \
        "mbarrier.try_wait.parity.acquire.cta.shared::cta.b64 p, [%1], %2;\n\t" \
        "selp.b32 %0, 1, 0, p;\n\t}" \
        : "=r"(_done) : "r"(_mbar), "r"(_parity) : "memory"); \
    if (!_done) { \
        asm volatile("{\n\t.reg .pred P1;\n\t" \
            "WAIT_LOOP_%=:\n\t" \
            "mbarrier.try_wait.parity.acquire.cta.shared::cta.b64 P1, [%0], %1, 0x989680;\n\t" \
            "@P1 bra.uni WAIT_DONE_%=;\n\t" \
            "bra.uni WAIT_LOOP_%=;\n\t" \
            "WAIT_DONE_%=:\n\t}" \
            :: "r"(_mbar), "r"(_parity) : "memory"); \
    } \
} while(0)

#if HAS_TCGEN05
#define TCGEN05_ALLOC(smem_result_addr, nCols) \
    asm volatile("tcgen05.alloc.cta_group::1.sync.aligned.shared::cta.b32 [%0], %1;" \
        :: "r"((uint32_t)(smem_result_addr)), "r"((uint32_t)(nCols)) : "memory")
#define TCGEN05_DEALLOC(tmem_addr, nCols) \
    asm volatile("tcgen05.dealloc.cta_group::1.sync.aligned.b32 %0, %1;" \
        :: "r"(tmem_addr), "r"((uint32_t)(nCols)))
#define TCGEN05_RELINQUISH_ALLOC_PERMIT() \
    asm volatile("tcgen05.relinquish_alloc_permit.cta_group::1.sync.aligned;")
#define TCGEN05_COMMIT(mbar_smem_addr) \
    asm volatile("tcgen05.commit.cta_group::1.mbarrier::arrive::one.shared::cluster.b64 [%0];" \
        :: "r"((uint32_t)(mbar_smem_addr)) : "memory")
#define TCGEN05_FENCE_BEFORE() asm volatile("tcgen05.fence::before_thread_sync;" ::: "memory")
#define TCGEN05_FENCE_AFTER()  asm volatile("tcgen05.fence::after_thread_sync;" ::: "memory")
#define TCGEN05_WAIT_LD()      asm volatile("tcgen05.wait::ld.sync.aligned;" ::: "memory")
#define TCGEN05_LD_32X32B_X32(r, tmem_addr) \
    asm volatile("tcgen05.ld.sync.aligned.32x32b.x32.b32 " \
        "{%0, %1, %2, %3, %4, %5, %6, %7, %8, %9, %10, %11, %12, %13, %14, %15, " \
        " %16, %17, %18, %19, %20, %21, %22, %23, %24, %25, %26, %27, %28, %29, %30, %31}, [%32];" \
        : "=r"((r)[0]),  "=r"((r)[1]),  "=r"((r)[2]),  "=r"((r)[3]), \
          "=r"((r)[4]),  "=r"((r)[5]),  "=r"((r)[6]),  "=r"((r)[7]), \
          "=r"((r)[8]),  "=r"((r)[9]),  "=r"((r)[10]), "=r"((r)[11]), \
          "=r"((r)[12]), "=r"((r)[13]), "=r"((r)[14]), "=r"((r)[15]), \
          "=r"((r)[16]), "=r"((r)[17]), "=r"((r)[18]), "=r"((r)[19]), \
          "=r"((r)[20]), "=r"((r)[21]), "=r"((r)[22]), "=r"((r)[23]), \
          "=r"((r)[24]), "=r"((r)[25]), "=r"((r)[26]), "=r"((r)[27]), \
          "=r"((r)[28]), "=r"((r)[29]), "=r"((r)[30]), "=r"((r)[31]) \
        : "r"(tmem_addr))
#define TMA_LOAD_3D(smem_addr, tensor_map, cx, cy, cz, mbar) \
    asm volatile("cp.async.bulk.tensor.3d.shared::cta.global.tile.mbarrier::complete_tx::bytes " \
        "[%0], [%1, {%2, %3, %4}], [%5];" \
        :: "r"((uint32_t)(smem_addr)), "l"(tensor_map), \
           "r"((int32_t)(cx)), "r"((int32_t)(cy)), "r"((int32_t)(cz)), \
           "r"((uint32_t)(mbar)) : "memory")

// SW64 smem descriptor (64-byte rows, BK=32 bf16).
static constexpr uint64_t SMEM_DESC_BASE_SW64 =
    (uint64_t(4)  << 61) | (uint64_t(1) << 46) | (uint64_t(32) << 32) | (uint64_t(1) << 16);
#define MAKE_SMEM_DESC(base_addr) \
    (SMEM_DESC_BASE_SW64 | ((uint64_t)((base_addr) >> 4) & 0x3FFF))

__device__ __forceinline__ void mma_f16_ss(uint32_t d_tmem, uint64_t a_desc,
                                           uint64_t b_desc, uint32_t idesc, bool acc)
{
    uint32_t en = acc ? 1u : 0u;
    asm volatile(
        "{\n\t.reg .pred p;\n\tsetp.ne.u32 p, %4, 0;\n\t"
        "tcgen05.mma.cta_group::1.kind::f16 [%0], %1, %2, %3, {%5, %5, %5, %5}, p;\n\t}"
        :: "r"(d_tmem), "l"(a_desc), "l"(b_desc), "r"(idesc), "r"(en), "r"(0u)
        : "memory");
}
#endif

static constexpr uint32_t IDESC_BF16_128x256 =
    (1u << 4) | (1u << 7) | (1u << 10) | ((256u / 8u) << 17) | ((128u / 16u) << 24);

// ===================== smem layout =====================
static constexpr int OFF_TMEM  = 0;
static constexpr int OFF_FULLB = 8;
static constexpr int OFF_DONEB = 40;
static constexpr int OFF_BIAS  = 128;
static constexpr int OFF_DATA  = 2048;
static constexpr int SMEM_BYTES = 198656;

__device__ __forceinline__ void split_store(float v, __nv_bfloat16* hi, __nv_bfloat16* lo)
{
    __nv_bfloat16 h = __float2bfloat16(v);
    *hi = h;
    *lo = __float2bfloat16(v - __bfloat162float(h));
}

// =====================================================================
// TMA-fed GEMM (r13 config): 128x256 tile, BK=32 (SW64), 4 stages x 48KB,
// warp-specialized, 1 CTA/SM. BIAS_MODE: 0=none,1=bias[m],2=bias[n].
// =====================================================================
template <int BIAS_MODE, bool OUT_BF16>
__global__ __launch_bounds__(256, 1)
void tc_gemm_tma(const __grid_constant__ CUtensorMap mapAhi,
                 const __grid_constant__ CUtensorMap mapAlo,
                 const __grid_constant__ CUtensorMap mapBhi,
                 const __grid_constant__ CUtensorMap mapBlo,
                 const __nv_bfloat16* __restrict__ Ahi,
                 const __nv_bfloat16* __restrict__ Alo,
                 const __nv_bfloat16* __restrict__ Bhi,
                 const __nv_bfloat16* __restrict__ Blo,
                 const float* __restrict__ bias,
                 float* __restrict__ Cf,
                 __nv_bfloat16* __restrict__ Chi,
                 __nv_bfloat16* __restrict__ Clo,
                 int M, int Nn, int K, int ldc,
                 long long strideA, long long strideB, long long strideC,
                 int zA, int zB)
{
    constexpr int NSTAGE = 4;
    constexpr int OFF_ALO = 8192;
    constexpr int OFF_BHI = 16384;
    constexpr int OFF_BLO = 32768;
    constexpr int STAGE_STRIDE = 49152;
    constexpr uint32_t TX_BYTES = 49152;

    extern __shared__ char smem[];
    const int tid = threadIdx.x;
    const int n0 = blockIdx.x * 256;
    const int m0 = blockIdx.y * 128;

    if (Cf)  Cf  += strideC * blockIdx.z;
    if (Chi) { Chi += strideC * blockIdx.z; Clo += strideC * blockIdx.z; }

#if HAS_TCGEN05
    const uint32_t sb = smem_to_u32(smem);
    const int wid = tid >> 5;
    const int zcA = zA ? blockIdx.z : 0;
    const int zcB = zB ? blockIdx.z : 0;

    if (tid == 0) {
        #pragma unroll
        for (int s = 0; s < NSTAGE; s++) {
            MBARRIER_INIT(sb + OFF_FULLB + 8 * s, 1);
            MBARRIER_INIT(sb + OFF_DONEB + 8 * s, 1);
        }
    }
    if (wid == 0) {
        TCGEN05_ALLOC(sb + OFF_TMEM, 256);
        TCGEN05_RELINQUISH_ALLOC_PERMIT();
    }
    if (BIAS_MODE == 2) {
        int n = n0 + tid;
        *(float*)(smem + OFF_BIAS + tid * 4) = (n < Nn) ? bias[n] : 0.0f;
    }
    __syncthreads();

    uint32_t tmem;
    asm volatile("ld.shared.b32 %0, [%1];" : "=r"(tmem) : "r"(sb + OFF_TMEM));

    const int nc = K / 32;

    if (tid == 32) {
        int phD[NSTAGE] = {};
        auto issue = [&](int c) {
            const int st = c & (NSTAGE - 1);
            const uint32_t fb  = sb + OFF_FULLB + 8 * st;
            const uint32_t b32 = sb + OFF_DATA + st * STAGE_STRIDE;
            MBARRIER_EXPECT_TX(fb, TX_BYTES);
            const int kt = c * 32;
            TMA_LOAD_3D(b32,           &mapAhi, kt, m0, zcA, fb);
            TMA_LOAD_3D(b32 + OFF_ALO, &mapAlo, kt, m0, zcA, fb);
            TMA_LOAD_3D(b32 + OFF_BHI, &mapBhi, kt, n0, zcB, fb);
            TMA_LOAD_3D(b32 + OFF_BLO, &mapBlo, kt, n0, zcB, fb);
        };
        #pragma unroll
        for (int c = 0; c < NSTAGE; c++) issue(c);
        for (int c = NSTAGE; c < nc; c++) {
            const int st = c & (NSTAGE - 1);
            MBARRIER_WAIT_PARITY(sb + OFF_DONEB + 8 * st, phD[st]);
            phD[st] ^= 1;
            issue(c);
        }
        #pragma unroll
        for (int s = 0; s < NSTAGE; s++)
            MBARRIER_WAIT_PARITY(sb + OFF_DONEB + 8 * s, phD[s]);
    }

    if (tid == 0) {
        int phF[NSTAGE] = {};
        for (int c = 0; c < nc; c++) {
            const int st = c & (NSTAGE - 1);
            MBARRIER_WAIT_PARITY(sb + OFF_FULLB + 8 * st, phF[st]);
            phF[st] ^= 1;

            const uint32_t b32 = sb + OFF_DATA + st * STAGE_STRIDE;
            const uint64_t dAh = MAKE_SMEM_DESC(b32);
            const uint64_t dAl = MAKE_SMEM_DESC(b32 + OFF_ALO);
            const uint64_t dBh = MAKE_SMEM_DESC(b32 + OFF_BHI);
            const uint64_t dBl = MAKE_SMEM_DESC(b32 + OFF_BLO);
            #pragma unroll
            for (int ks = 0; ks < 2; ks++) {
                const uint64_t o = (uint64_t)(ks * 2);
                mma_f16_ss(tmem, dAh + o, dBh + o, IDESC_BF16_128x256,
                           !(c == 0 && ks == 0));
                mma_f16_ss(tmem, dAh + o, dBl + o, IDESC_BF16_128x256, true);
                mma_f16_ss(tmem, dAl + o, dBh + o, IDESC_BF16_128x256, true);
            }
            TCGEN05_COMMIT(sb + OFF_DONEB + 8 * st);
        }
    }

    __syncthreads();
    TCGEN05_FENCE_AFTER();

    if (tid < 128) {
        const int m = m0 + tid;
        const bool mok = (m < M);
        const float bm = (BIAS_MODE == 1 && mok) ? bias[m] : 0.0f;
        const float* bs = (const float*)(smem + OFF_BIAS);
        #pragma unroll
        for (int b = 0; b < 8; b++) {
            uint32_t r[32];
            TCGEN05_LD_32X32B_X32(r, tmem + b * 32);
            TCGEN05_WAIT_LD();
            if (mok) {
                #pragma unroll
                for (int j = 0; j < 8; j++) {
                    const int nc2 = b * 32 + j * 4;
                    const int n = n0 + nc2;
                    if (n + 4 <= Nn) {
                        float v[4];
                        #pragma unroll
                        for (int e = 0; e < 4; e++) {
                            v[e] = __uint_as_float(r[j * 4 + e]);
                            if (BIAS_MODE == 1) v[e] += bm;
                            if (BIAS_MODE == 2) v[e] += bs[nc2 + e];
                        }
                        if (OUT_BF16) {
                            __nv_bfloat16 h[4], l[4];
                            #pragma unroll
                            for (int e = 0; e < 4; e++) {
                                h[e] = __float2bfloat16(v[e]);
                                l[e] = __float2bfloat16(v[e] - __bfloat162float(h[e]));
                            }
                            uint2 hp, lp;
                            memcpy(&hp.x, &h[0], 4); memcpy(&hp.y, &h[2], 4);
                            memcpy(&lp.x, &l[0], 4); memcpy(&lp.y, &l[2], 4);
                            *(uint2*)(Chi + (long long)m * ldc + n) = hp;
                            *(uint2*)(Clo + (long long)m * ldc + n) = lp;
                        } else {
                            float4 o; o.x = v[0]; o.y = v[1]; o.z = v[2]; o.w = v[3];
                            *(float4*)(Cf + (long long)m * ldc + n) = o;
                        }
                    }
                }
            }
        }
    }
    TCGEN05_FENCE_BEFORE();
    __syncthreads();
    if (tid == 0) {
        #pragma unroll
        for (int s = 0; s < NSTAGE; s++) {
            mbarrier_inval(sb + OFF_FULLB + 8 * s);
            mbarrier_inval(sb + OFF_DONEB + 8 * s);
        }
    }
    if (wid == 0) TCGEN05_DEALLOC(tmem, 256);

#else
    Ahi += strideA * blockIdx.z;  Alo += strideA * blockIdx.z;
    Bhi += strideB * blockIdx.z;  Blo += strideB * blockIdx.z;
    for (int idx = tid; idx < 128 * 256; idx += 256) {
        const int i = idx >> 8, j = idx & 255;
        const int m = m0 + i, n = n0 + j;
        if (m < M && n < Nn) {
            float acc = 0.f;
            for (int k = 0; k < K; k++) {
                float a = __bfloat162float(Ahi[(long long)m * K + k]) +
                          __bfloat162float(Alo[(long long)m * K + k]);
                float b = __bfloat162float(Bhi[(long long)n * K + k]) +
                          __bfloat162float(Blo[(long long)n * K + k]);
                acc += a * b;
            }
            if (BIAS_MODE == 1) acc += bias[m];
            if (BIAS_MODE == 2) acc += bias[n];
            if (OUT_BF16)
                split_store(acc, Chi + (long long)m * ldc + n, Clo + (long long)m * ldc + n);
            else
                Cf[(long long)m * ldc + n] = acc;
        }
    }
#endif
}

// ===================== zero sx =====================
__global__ void zero_sx(float* sx)
{
    const int i = blockIdx.x * 256 + threadIdx.x;
    if (i < N_B * C_DIM) sx[i] = 0.0f;
}

// ===================== split x into BOTH layouts + row sums =====================
// xs: [n][c][s] (straight split), xt: [n][s][c] (transposed), sx[n][c] += sums.
__global__ __launch_bounds__(256)
void split_x_both(const float* __restrict__ bf,
                  __nv_bfloat16* __restrict__ xs_hi, __nv_bfloat16* __restrict__ xs_lo,
                  __nv_bfloat16* __restrict__ xt_hi, __nv_bfloat16* __restrict__ xt_lo,
                  float* __restrict__ sx)
{
    __shared__ float t[64][65];
    const int n = blockIdx.z;
    const int hw0 = blockIdx.x * 64;
    const int c0 = blockIdx.y * 64;
    const int tid = threadIdx.x;

    const float* src = bf + (size_t)n * C_DIM * HW_DIM;
    {
        const int r  = tid >> 2;          // c row 0..63
        const int cb = (tid & 3) * 16;    // hw offset
        const float* p = src + (size_t)(c0 + r) * HW_DIM + hw0 + cb;
        float f[16];
        #pragma unroll
        for (int i = 0; i < 4; i++) {
            float4 v = *(const float4*)(p + i * 4);
            f[i*4+0]=v.x; f[i*4+1]=v.y; f[i*4+2]=v.z; f[i*4+3]=v.w;
            t[r][cb + i*4+0]=v.x; t[r][cb + i*4+1]=v.y;
            t[r][cb + i*4+2]=v.z; t[r][cb + i*4+3]=v.w;
        }
        // straight split -> xs [c][s]
        __nv_bfloat16 h[16], l[16];
        float s = 0.f;
        #pragma unroll
        for (int j = 0; j < 16; j++) {
            s += f[j];
            h[j] = __float2bfloat16(f[j]);
            l[j] = __float2bfloat16(f[j] - __bfloat162float(h[j]));
        }
        const size_t o = (size_t)n * C_DIM * HW_DIM +
                         (size_t)(c0 + r) * HW_DIM + hw0 + cb;
        uint4 hv0, hv1, lv0, lv1;
        memcpy(&hv0, &h[0], 16); memcpy(&hv1, &h[8], 16);
        memcpy(&lv0, &l[0], 16); memcpy(&lv1, &l[8], 16);
        *(uint4*)(xs_hi + o)     = hv0;
        *(uint4*)(xs_hi + o + 8) = hv1;
        *(uint4*)(xs_lo + o)     = lv0;
        *(uint4*)(xs_lo + o + 8) = lv1;
        // row-sum across the 4 threads of this c-row (consecutive lanes)
        #pragma unroll
        for (int off = 1; off < 4; off <<= 1)
            s += __shfl_xor_sync(0xffffffffu, s, off);
        if ((tid & 3) == 0)
            atomicAdd(&sx[n * C_DIM + c0 + r], s);
    }
    __syncthreads();
    {
        const int sl   = tid >> 2;
        const int cseg = (tid & 3) * 16;
        __nv_bfloat16 h[16], l[16];
        #pragma unroll
        for (int j = 0; j < 16; j++) {
            const float v = t[cseg + j][sl];
            h[j] = __float2bfloat16(v);
            l[j] = __float2bfloat16(v - __bfloat162float(h[j]));
        }
        const size_t o = (size_t)n * HW_DIM * C_DIM +
                         (size_t)(hw0 + sl) * C_DIM + c0 + cseg;
        uint4 hv0, hv1, lv0, lv1;
        memcpy(&hv0, &h[0], 16); memcpy(&hv1, &h[8], 16);
        memcpy(&lv0, &l[0], 16); memcpy(&lv1, &l[8], 16);
        *(uint4*)(xt_hi + o)     = hv0;
        *(uint4*)(xt_hi + o + 8) = hv1;
        *(uint4*)(xt_lo + o)     = lv0;
        *(uint4*)(xt_lo + o + 8) = lv1;
    }
}

// ===================== split W (three weights) =====================
__global__ __launch_bounds__(256)
void split_w3(const float* __restrict__ Wq, const float* __restrict__ Wk,
              const float* __restrict__ Wv,
              __nv_bfloat16* __restrict__ whi, __nv_bfloat16* __restrict__ wlo)
{
    const int which = blockIdx.y;
    const float* W = (which == 0) ? Wq : (which == 1) ? Wk : Wv;
    const size_t base = (size_t)which * D_DIM * C_DIM;
    const int i4 = (blockIdx.x * 256 + threadIdx.x) * 4;
    if (i4 < D_DIM * C_DIM) {
        float4 v = *(const float4*)(W + i4);
        __nv_bfloat16 h[4], l[4];
        float f[4] = {v.x, v.y, v.z, v.w};
        #pragma unroll
        for (int e = 0; e < 4; e++) {
            h[e] = __float2bfloat16(f[e]);
            l[e] = __float2bfloat16(f[e] - __bfloat162float(h[e]));
        }
        uint2 hp, lp;
        memcpy(&hp, &h[0], 8);
        memcpy(&lp, &l[0], 8);
        *(uint2*)(whi + base + i4) = hp;
        *(uint2*)(wlo + base + i4) = lp;
    }
}

// ===================== split G (fp32 -> bf16 planes) =====================
__global__ __launch_bounds__(256)
void split_g(const float* __restrict__ G,
             __nv_bfloat16* __restrict__ ghi, __nv_bfloat16* __restrict__ glo)
{
    const long long i4 = ((long long)blockIdx.x * 256 + threadIdx.x) * 4;
    if (i4 < (long long)N_B * C_DIM * C_DIM) {
        float4 v = *(const float4*)(G + i4);
        __nv_bfloat16 h[4], l[4];
        float f[4] = {v.x, v.y, v.z, v.w};
        #pragma unroll
        for (int e = 0; e < 4; e++) {
            h[e] = __float2bfloat16(f[e]);
            l[e] = __float2bfloat16(f[e] - __bfloat162float(h[e]));
        }
        uint2 hp, lp;
        memcpy(&hp, &h[0], 8);
        memcpy(&lp, &l[0], 8);
        *(uint2*)(ghi + i4) = hp;
        *(uint2*)(glo + i4) = lp;
    }
}

// ===================== u = Wq*sx, v = Wk*sx per batch =====================
__global__ __launch_bounds__(128)
void uv_kernel(const float* __restrict__ Wq, const float* __restrict__ Wk,
               const float* __restrict__ sx,
               float* __restrict__ u, float* __restrict__ vv)
{
    const int d = blockIdx.x * 128 + threadIdx.x;
    const int n = blockIdx.y;
    const float* sxn = sx + n * C_DIM;
    float su = 0.f, sv = 0.f;
    for (int c = 0; c < C_DIM; c += 4) {
        float4 s4 = *(const float4*)(sxn + c);
        float4 q4 = *(const float4*)(Wq + (size_t)d * C_DIM + c);
        float4 k4 = *(const float4*)(Wk + (size_t)d * C_DIM + c);
        su += q4.x*s4.x + q4.y*s4.y + q4.z*s4.z + q4.w*s4.w;
        sv += k4.x*s4.x + k4.y*s4.y + k4.z*s4.z + k4.w*s4.w;
    }
    u[n * D_DIM + d]  = su;
    vv[n * D_DIM + d] = sv;
}

// ===================== softmax with rank-1 bias correction =====================
// S'[d][e] = Sg[d][e] + bq[d]*v[e] + u[d]*bk[e] + HW*bq[d]*bk[e]
__global__ __launch_bounds__(128)
void softmax_corr(const float* __restrict__ Sg,
                  const float* __restrict__ u, const float* __restrict__ vv,
                  const float* __restrict__ bq, const float* __restrict__ bk,
                  __nv_bfloat16* __restrict__ ahi, __nv_bfloat16* __restrict__ alo)
{
    const long long row = blockIdx.x;
    const int n = (int)(row >> 9);          // /512
    const int d = (int)(row & 511);
    const float* p = Sg + row * D_DIM;
    const int t = threadIdx.x;

    const float bqd = bq[d];
    const float ud  = u[n * D_DIM + d];
    const float cst = (float)HW_DIM * bqd;  // multiplies bk[e]

    float4 v = *(const float4*)(p + t * 4);
    float4 v4 = *(const float4*)(vv + n * D_DIM + t * 4);
    float4 b4 = *(const float4*)(bk + t * 4);
    float f[4];
    f[0] = v.x + bqd * v4.x + (ud + cst) * b4.x;
    f[1] = v.y + bqd * v4.y + (ud + cst) * b4.y;
    f[2] = v.z + bqd * v4.z + (ud + cst) * b4.z;
    f[3] = v.w + bqd * v4.w + (ud + cst) * b4.w;

    __shared__ float red_max[4];
    __shared__ float red_sum[4];

    float m = fmaxf(fmaxf(f[0], f[1]), fmaxf(f[2], f[3]));
    #pragma unroll
    for (int o = 16; o > 0; o >>= 1)
        m = fmaxf(m, __shfl_xor_sync(0xffffffffu, m, o));
    if ((t & 31) == 0) red_max[t >> 5] = m;
    __syncthreads();
    float rowmax = fmaxf(fmaxf(red_max[0], red_max[1]), fmaxf(red_max[2], red_max[3]));

    float e[4];
    #pragma unroll
    for (int i = 0; i < 4; i++) e[i] = __expf(f[i] - rowmax);
    float s = e[0] + e[1] + e[2] + e[3];
    #pragma unroll
    for (int o = 16; o > 0; o >>= 1)
        s += __shfl_xor_sync(0xffffffffu, s, o);
    if ((t & 31) == 0) red_sum[t >> 5] = s;
    __syncthreads();
    const float inv = 1.0f / (red_sum[0] + red_sum[1] + red_sum[2] + red_sum[3]);

    __nv_bfloat16 h[4], l[4];
    #pragma unroll
    for (int i = 0; i < 4; i++) {
        const float pv = e[i] * inv;
        h[i] = __float2bfloat16(pv);
        l[i] = __float2bfloat16(pv - __bfloat162float(h[i]));
    }
    uint2 hp, lp;
    memcpy(&hp, &h[0], 8);
    memcpy(&lp, &l[0], 8);
    *(uint2*)(ahi + row * D_DIM + t * 4) = hp;
    *(uint2*)(alo + row * D_DIM + t * 4) = lp;
}

// ===================== host: tensormap encode =====================
typedef CUresult (*EncodeTiledFn)(
    CUtensorMap*, CUtensorMapDataType, cuuint32_t, void*,
    const cuuint64_t*, const cuuint64_t*, const cuuint32_t*, const cuuint32_t*,
    CUtensorMapInterleave, CUtensorMapSwizzle, CUtensorMapL2promotion,
    CUtensorMapFloatOOBfill);

static EncodeTiledFn get_encode_fn()
{
    static EncodeTiledFn fn = nullptr;
    if (!fn) {
        cudaDriverEntryPointQueryResult st;
        void* p = nullptr;
        cudaGetDriverEntryPoint("cuTensorMapEncodeTiled", &p,
                                cudaEnableDefault, &st);
        fn = (EncodeTiledFn)p;
    }
    return fn;
}

static void make_map(CUtensorMap* m, const void* base,
                     unsigned long long K, unsigned long long rows,
                     unsigned long long batch, unsigned boxRows)
{
    cuuint64_t dims[3]    = {K, rows, batch};
    cuuint64_t strides[2] = {K * 2ull, K * rows * 2ull};
    cuuint32_t box[3]     = {32u, boxRows, 1u};
    cuuint32_t es[3]      = {1u, 1u, 1u};
    get_encode_fn()(m, CU_TENSOR_MAP_DATA_TYPE_BFLOAT16, 3, (void*)base,
                    dims, strides, box, es,
                    CU_TENSOR_MAP_INTERLEAVE_NONE, CU_TENSOR_MAP_SWIZZLE_64B,
                    CU_TENSOR_MAP_L2_PROMOTION_L2_128B,
                    CU_TENSOR_MAP_FLOAT_OOB_FILL_NONE);
}

extern "C" void kernel_launch(void* const* d_in, const int* in_sizes, int n_in,
                              void* d_out, int out_size)
{
    (void)in_sizes; (void)n_in; (void)out_size;
    const float* bf = (const float*)d_in[0];  // [N, C, HW]
    const float* Wq = (const float*)d_in[1];  // [D, C]
    const float* bq = (const float*)d_in[2];  // [D]
    const float* Wk = (const float*)d_in[3];
    const float* bk = (const float*)d_in[4];
    const float* Wv = (const float*)d_in[5];
    const float* bv = (const float*)d_in[6];
    float* out = (float*)d_out;               // [N, D, HW]

    __nv_bfloat16 *xth, *xtl, *xsh, *xsl, *wh, *wl, *vh, *vl, *ah, *al;
    __nv_bfloat16 *ghp, *glp, *t1h, *t1l;
    float *Sp, *Gp, *sxp, *up, *vvp;
    cudaGetSymbolAddress((void**)&xth, g_xt_hi);
    cudaGetSymbolAddress((void**)&xtl, g_xt_lo);
    cudaGetSymbolAddress((void**)&xsh, g_xs_hi);
    cudaGetSymbolAddress((void**)&xsl, g_xs_lo);
    cudaGetSymbolAddress((void**)&wh, g_w_hi);
    cudaGetSymbolAddress((void**)&wl, g_w_lo);
    cudaGetSymbolAddress((void**)&vh, g_v_hi);
    cudaGetSymbolAddress((void**)&vl, g_v_lo);
    cudaGetSymbolAddress((void**)&ah, g_att_hi);
    cudaGetSymbolAddress((void**)&al, g_att_lo);
    cudaGetSymbolAddress((void**)&ghp, g_g_hi);
    cudaGetSymbolAddress((void**)&glp, g_g_lo);
    cudaGetSymbolAddress((void**)&t1h, g_t1_hi);
    cudaGetSymbolAddress((void**)&t1l, g_t1_lo);
    cudaGetSymbolAddress((void**)&Sp, g_S);
    cudaGetSymbolAddress((void**)&Gp, g_G);
    cudaGetSymbolAddress((void**)&sxp, g_sx);
    cudaGetSymbolAddress((void**)&up, g_u);
    cudaGetSymbolAddress((void**)&vvp, g_vv);

    cudaFuncSetAttribute(tc_gemm_tma<0, false>,
        cudaFuncAttributeMaxDynamicSharedMemorySize, SMEM_BYTES);
    cudaFuncSetAttribute(tc_gemm_tma<0, true>,
        cudaFuncAttributeMaxDynamicSharedMemorySize, SMEM_BYTES);
    cudaFuncSetAttribute(tc_gemm_tma<2, true>,
        cudaFuncAttributeMaxDynamicSharedMemorySize, SMEM_BYTES);

    const dim3 blk(256);
    const size_t WSZ = (size_t)D_DIM * C_DIM;
    const long long sX  = (long long)HW_DIM * C_DIM;
    const long long sV  = (long long)HW_DIM * D_DIM;
    const long long sCC = (long long)C_DIM * C_DIM;   // G / T1 / S per-batch

    // 0) zero sx, split x into both layouts (+sx), split weights
    zero_sx<<<(N_B * C_DIM + 255) / 256, blk>>>(sxp);
    split_x_both<<<dim3(HW_DIM / 64, C_DIM / 64, N_B), blk>>>(
        bf, xsh, xsl, xth, xtl, sxp);
    split_w3<<<dim3((D_DIM * C_DIM / 4 + 255) / 256, 3), blk>>>(Wq, Wk, Wv, wh, wl);

    // tensormaps
    CUtensorMap mXsA_h, mXsA_l, mXsB_h, mXsB_l;      // xs [c][s], K=HW
    CUtensorMap mXtA_h, mXtA_l;                      // xt [s][c], K=C (A for Vproj)
    CUtensorMap mWqA_h, mWqA_l, mWkB_h, mWkB_l, mWvB_h, mWvB_l;
    CUtensorMap mG_h, mG_l, mT1_h, mT1_l;
    CUtensorMap mV_h, mV_l, mAtt_h, mAtt_l;
    make_map(&mXsA_h, xsh, HW_DIM, C_DIM, N_B, 128);
    make_map(&mXsA_l, xsl, HW_DIM, C_DIM, N_B, 128);
    make_map(&mXsB_h, xsh, HW_DIM, C_DIM, N_B, 256);
    make_map(&mXsB_l, xsl, HW_DIM, C_DIM, N_B, 256);
    make_map(&mXtA_h, xth, C_DIM, HW_DIM, N_B, 128);
    make_map(&mXtA_l, xtl, C_DIM, HW_DIM, N_B, 128);
    make_map(&mWqA_h, wh + 0 * WSZ, C_DIM, D_DIM, 1, 128);
    make_map(&mWqA_l, wl + 0 * WSZ, C_DIM, D_DIM, 1, 128);
    make_map(&mWkB_h, wh + 1 * WSZ, C_DIM, D_DIM, 1, 256);
    make_map(&mWkB_l, wl + 1 * WSZ, C_DIM, D_DIM, 1, 256);
    make_map(&mWvB_h, wh + 2 * WSZ, C_DIM, D_DIM, 1, 256);
    make_map(&mWvB_l, wl + 2 * WSZ, C_DIM, D_DIM, 1, 256);
    make_map(&mG_h, ghp, C_DIM, C_DIM, N_B, 256);    // B for T1 (symmetric G)
    make_map(&mG_l, glp, C_DIM, C_DIM, N_B, 256);
    make_map(&mT1_h, t1h, C_DIM, D_DIM, N_B, 128);   // A for S
    make_map(&mT1_l, t1l, C_DIM, D_DIM, N_B, 128);
    make_map(&mV_h, vh, D_DIM, HW_DIM, N_B, 256);    // B for out
    make_map(&mV_l, vl, D_DIM, HW_DIM, N_B, 256);
    make_map(&mAtt_h, ah, D_DIM, D_DIM, N_B, 128);   // A for out
    make_map(&mAtt_l, al, D_DIM, D_DIM, N_B, 128);

    // 1) G = x.x^T: M=c(512), N=c'(512), K=s(3136). Out fp32.
    const dim3 g_G(C_DIM / 256, C_DIM / 128, N_B);               // (2, 4, 16)
    tc_gemm_tma<0, false><<<g_G, blk, SMEM_BYTES>>>(
        mXsA_h, mXsA_l, mXsB_h, mXsB_l,
        xsh, xsl, xsh, xsl, nullptr, Gp, nullptr, nullptr,
        C_DIM, C_DIM, HW_DIM, C_DIM, sX, sX, sCC, 1, 1);

    // 1b) V proj: M=s(3136), N=d(512), K=c(512). A=xT, B=Wv. (+bias[n])
    const dim3 g_v(D_DIM / 256, (HW_DIM + 127) / 128, N_B);      // (2, 25, 16)
    tc_gemm_tma<2, true><<<g_v, blk, SMEM_BYTES>>>(
        mXtA_h, mXtA_l, mWvB_h, mWvB_l,
        xth, xtl, wh + 2 * WSZ, wl + 2 * WSZ, bv, nullptr, vh, vl,
        HW_DIM, D_DIM, C_DIM, D_DIM, sX, 0, sV, 1, 0);

    // 2) small ops: u/v rank-1 terms, split G
    uv_kernel<<<dim3(D_DIM / 128, N_B), 128>>>(Wq, Wk, sxp, up, vvp);
    split_g<<<((N_B * C_DIM * C_DIM / 4) + 255) / 256, blk>>>(Gp, ghp, glp);

    // 3) T1 = Wq*G: M=d(512), N=c'(512), K=c(512). Out bf16 planes.
    const dim3 g_t1(C_DIM / 256, D_DIM / 128, N_B);              // (2, 4, 16)
    tc_gemm_tma<0, true><<<g_t1, blk, SMEM_BYTES>>>(
        mWqA_h, mWqA_l, mG_h, mG_l,
        wh + 0 * WSZ, wl + 0 * WSZ, ghp, glp, nullptr, nullptr, t1h, t1l,
        D_DIM, C_DIM, C_DIM, C_DIM, 0, sCC, sCC, 0, 1);

    // 4) Sg = T1*Wk^T: M=d(512), N=e(512), K=c'(512). Out fp32.
    const dim3 g_s(D_DIM / 256, D_DIM / 128, N_B);               // (2, 4, 16)
    tc_gemm_tma<0, false><<<g_s, blk, SMEM_BYTES>>>(
        mT1_h, mT1_l, mWkB_h, mWkB_l,
        t1h, t1l, wh + 1 * WSZ, wl + 1 * WSZ, nullptr, Sp, nullptr, nullptr,
        D_DIM, D_DIM, C_DIM, D_DIM, sCC, 0, sCC, 1, 0);

    // 5) softmax with rank-1 correction -> att planes
    softmax_corr<<<N_B * D_DIM, 128>>>(Sp, up, vvp, bq, bk, ah, al);

    // 6) out: M=d(512), N=s(3136), K=e(512). A=att planes, B=V planes. fp32.
    const dim3 g_out((HW_DIM + 255) / 256, D_DIM / 128, N_B);    // (13, 4, 16)
    tc_gemm_tma<0, false><<<g_out, blk, SMEM_BYTES>>>(
        mAtt_h, mAtt_l, mV_h, mV_l,
        ah, al, vh, vl, nullptr, out, nullptr, nullptr,
        D_DIM, HW_DIM, D_DIM, HW_DIM, sCC, sV, (long long)D_DIM * HW_DIM, 1, 1);
}